// round 2
// baseline (speedup 1.0000x reference)
#include <cuda_runtime.h>
#include <cuda_bf16.h>
#include <math.h>

#define T_LEN 4096
#define D_DIM 512
#define TR_DIM 64
#define CC_DIM 64
#define F_DIM 8192   // 2*TR*CC
#define L_NUM 3

// ------------------------- scratch (device globals; no alloc) ---------------
__device__ float g_X[(size_t)T_LEN * D_DIM];          // running residual x
__device__ float g_atr[(size_t)T_LEN * TR_DIM];       // |tr|
__device__ float g_act[(size_t)T_LEN * CC_DIM];       // |ct|
__device__ float g_inv[T_LEN];                        // 1/(1e-8 + S_tr*S_ct)
__device__ float g_scaled[(size_t)T_LEN * F_DIM];     // scan features (134MB)
__device__ float g_h[(size_t)T_LEN * D_DIM];          // hidden after GEMM0
__device__ float g_z[(size_t)T_LEN * D_DIM];          // layer output z

// ------------------------- small utility kernels ----------------------------
__global__ void copy_kernel(float* __restrict__ dst, const float* __restrict__ src, int n) {
    int i = blockIdx.x * blockDim.x + threadIdx.x;
    int stride = gridDim.x * blockDim.x;
    for (; i < n; i += stride) dst[i] = src[i];
}

__global__ void residual_kernel(float* __restrict__ x, const float* __restrict__ z, int n) {
    int i = blockIdx.x * blockDim.x + threadIdx.x;
    int stride = gridDim.x * blockDim.x;
    for (; i < n; i += stride) x[i] += z[i];
}

// ------------------------- projections: |tr|, |ct|, inv-sum ------------------
// one block per token t, 128 threads: tid<64 -> tr row, tid>=64 -> ct row
__global__ __launch_bounds__(128) void proj_kernel(
    const float* __restrict__ X, const float* __restrict__ Wtr,
    const float* __restrict__ Wc, float* __restrict__ atr,
    float* __restrict__ act, float* __restrict__ inv)
{
    __shared__ float4 xs[D_DIM / 4];
    __shared__ float red[128];
    int t = blockIdx.x;
    int tid = threadIdx.x;

    const float4* xrow = (const float4*)(X + (size_t)t * D_DIM);
    xs[tid] = xrow[tid];
    __syncthreads();

    const float4* W = (tid < 64)
        ? (const float4*)(Wtr + (size_t)tid * D_DIM)
        : (const float4*)(Wc + (size_t)(tid - 64) * D_DIM);

    float s = 0.f;
#pragma unroll 8
    for (int k = 0; k < D_DIM / 4; ++k) {
        float4 w = W[k], x4 = xs[k];
        s += w.x * x4.x + w.y * x4.y + w.z * x4.z + w.w * x4.w;
    }
    float av = fabsf(s);
    if (tid < 64) atr[(size_t)t * TR_DIM + tid] = av;
    else          act[(size_t)t * CC_DIM + tid - 64] = av;

    red[tid] = av;
    __syncthreads();
#pragma unroll
    for (int off = 32; off > 0; off >>= 1) {
        if ((tid & 63) < off) red[tid] += red[tid + off];
        __syncthreads();
    }
    if (tid == 0) inv[t] = 1.f / (1e-8f + red[0] * red[64]);
}

// ------------------------- segmented complex scan + feature map -------------
// grid = TR (i), block = CC threads (j). s_t = (start? 0 : s_{t-1})*d + p_t
__global__ __launch_bounds__(CC_DIM) void scan_kernel(
    const float* __restrict__ atr, const float* __restrict__ act,
    const float* __restrict__ inv, const unsigned int* __restrict__ start,
    const float* __restrict__ a, const float* __restrict__ b,
    const float* __restrict__ st0, float* __restrict__ scaled)
{
    int i = blockIdx.x;
    int j = threadIdx.x;
    float mag_d = expf(-fabsf(a[i]));
    float bj = b[j];
    float dr = mag_d * cosf(bj);
    float di = mag_d * sinf(bj);

    float sr = st0[i * CC_DIM + j];  // state (real; imag 0)
    float si = 0.f;
    int c = i * CC_DIM + j;

#pragma unroll 4
    for (int t = 0; t < T_LEN; ++t) {
        float at = atr[(size_t)t * TR_DIM + i];   // broadcast within block
        float ac = act[(size_t)t * CC_DIM + j];   // coalesced
        float p = at * ac * inv[t];
        if (start[t] != 0u) { sr = 0.f; si = 0.f; }
        float nsr = sr * dr - si * di + p;
        float nsi = sr * di + si * dr;
        sr = nsr; si = nsi;
        float r = sqrtf(sr * sr + si * si);
        float f = (r > 1e-30f) ? (log1pf(r) / r) : 1.0f;
        scaled[(size_t)t * F_DIM + c]                = f * si;  // mag*sin(ang)
        scaled[(size_t)t * F_DIM + (TR_DIM*CC_DIM) + c] = f * sr;  // mag*cos(ang)
    }
}

// ------------------------- SGEMM: C = A @ B^T (A MxK, B NxK) -----------------
#define BM 128
#define BN 64
#define BK 16
__global__ __launch_bounds__(256) void sgemm_tn(
    const float* __restrict__ A, const float* __restrict__ B,
    float* __restrict__ C, int M, int N, int K)
{
    __shared__ float As[BK][BM];
    __shared__ float Bs[BK][BN];

    int tid = threadIdx.x;                 // 0..255
    int bm = blockIdx.y * BM;
    int bn = blockIdx.x * BN;
    int tx = tid & 15;                     // n direction (4 cols each)
    int ty = tid >> 4;                     // m direction (8 rows each)

    float acc[8][4];
#pragma unroll
    for (int ii = 0; ii < 8; ++ii)
#pragma unroll
        for (int jj = 0; jj < 4; ++jj) acc[ii][jj] = 0.f;

    for (int k0 = 0; k0 < K; k0 += BK) {
        // load A tile: 128x16 = 512 float4, 2 per thread
#pragma unroll
        for (int r = 0; r < 2; ++r) {
            int idx = tid + r * 256;
            int row = idx >> 2, c4 = idx & 3;
            float4 v = *(const float4*)(A + (size_t)(bm + row) * K + k0 + c4 * 4);
            As[c4 * 4 + 0][row] = v.x;
            As[c4 * 4 + 1][row] = v.y;
            As[c4 * 4 + 2][row] = v.z;
            As[c4 * 4 + 3][row] = v.w;
        }
        // load B tile: 64x16 = 256 float4, 1 per thread
        {
            int row = tid >> 2, c4 = tid & 3;
            float4 v = *(const float4*)(B + (size_t)(bn + row) * K + k0 + c4 * 4);
            Bs[c4 * 4 + 0][row] = v.x;
            Bs[c4 * 4 + 1][row] = v.y;
            Bs[c4 * 4 + 2][row] = v.z;
            Bs[c4 * 4 + 3][row] = v.w;
        }
        __syncthreads();

#pragma unroll
        for (int kk = 0; kk < BK; ++kk) {
            float4 a0 = *(const float4*)&As[kk][ty * 8];
            float4 a1 = *(const float4*)&As[kk][ty * 8 + 4];
            float4 bf = *(const float4*)&Bs[kk][tx * 4];
            float av[8] = {a0.x, a0.y, a0.z, a0.w, a1.x, a1.y, a1.z, a1.w};
            float bv[4] = {bf.x, bf.y, bf.z, bf.w};
#pragma unroll
            for (int ii = 0; ii < 8; ++ii)
#pragma unroll
                for (int jj = 0; jj < 4; ++jj) acc[ii][jj] += av[ii] * bv[jj];
        }
        __syncthreads();
    }

#pragma unroll
    for (int ii = 0; ii < 8; ++ii) {
        float4 v = make_float4(acc[ii][0], acc[ii][1], acc[ii][2], acc[ii][3]);
        *(float4*)(C + (size_t)(bm + ty * 8 + ii) * N + bn + tx * 4) = v;
    }
}

// ------------------------- layernorm + leaky_relu (in place) ----------------
// one block per row (D=512), 128 threads x 4 elems
__global__ __launch_bounds__(128) void ln_leaky_kernel(
    float* __restrict__ Z, const float* __restrict__ bias,
    const float* __restrict__ g, const float* __restrict__ beta)
{
    __shared__ float sh[8];
    int t = blockIdx.x;
    int tid = threadIdx.x;
    float* row = Z + (size_t)t * D_DIM;

    float v[4];
    float s = 0.f;
#pragma unroll
    for (int q = 0; q < 4; ++q) {
        int idx = tid + q * 128;
        v[q] = row[idx] + bias[idx];
        s += v[q];
    }
#pragma unroll
    for (int off = 16; off > 0; off >>= 1) s += __shfl_xor_sync(0xffffffffu, s, off);
    if ((tid & 31) == 0) sh[tid >> 5] = s;
    __syncthreads();
    float mean = (sh[0] + sh[1] + sh[2] + sh[3]) * (1.f / D_DIM);

    float vs = 0.f;
#pragma unroll
    for (int q = 0; q < 4; ++q) { float d = v[q] - mean; vs += d * d; }
#pragma unroll
    for (int off = 16; off > 0; off >>= 1) vs += __shfl_xor_sync(0xffffffffu, vs, off);
    if ((tid & 31) == 0) sh[4 + (tid >> 5)] = vs;
    __syncthreads();
    float var = (sh[4] + sh[5] + sh[6] + sh[7]) * (1.f / D_DIM);
    float rstd = rsqrtf(var + 1e-5f);

#pragma unroll
    for (int q = 0; q < 4; ++q) {
        int idx = tid + q * 128;
        float y = (v[q] - mean) * rstd * g[idx] + beta[idx];
        row[idx] = (y > 0.f) ? y : 0.01f * y;
    }
}

// ------------------------- launch ------------------------------------------
extern "C" void kernel_launch(void* const* d_in, const int* in_sizes, int n_in,
                              void* d_out, int out_size)
{
    const float* x     = (const float*)d_in[0];
    const float* state = (const float*)d_in[1];
    const unsigned int* start = (const unsigned int*)d_in[2];
    const float* Wtr   = (const float*)d_in[3];
    const float* Wc    = (const float*)d_in[4];
    const float* a     = (const float*)d_in[5];
    const float* b     = (const float*)d_in[6];
    const float* W0    = (const float*)d_in[7];
    const float* b0    = (const float*)d_in[8];
    const float* g0    = (const float*)d_in[9];
    const float* be0   = (const float*)d_in[10];
    const float* W1    = (const float*)d_in[11];
    const float* b1    = (const float*)d_in[12];
    const float* g1    = (const float*)d_in[13];
    const float* be1   = (const float*)d_in[14];
    float* out = (float*)d_out;

    float *pX, *pAtr, *pAct, *pInv, *pScaled, *pH, *pZ;
    cudaGetSymbolAddress((void**)&pX, g_X);
    cudaGetSymbolAddress((void**)&pAtr, g_atr);
    cudaGetSymbolAddress((void**)&pAct, g_act);
    cudaGetSymbolAddress((void**)&pInv, g_inv);
    cudaGetSymbolAddress((void**)&pScaled, g_scaled);
    cudaGetSymbolAddress((void**)&pH, g_h);
    cudaGetSymbolAddress((void**)&pZ, g_z);

    const int ND = T_LEN * D_DIM;
    copy_kernel<<<512, 256>>>(pX, x, ND);

    for (int l = 0; l < L_NUM; ++l) {
        proj_kernel<<<T_LEN, 128>>>(pX, Wtr + (size_t)l * TR_DIM * D_DIM,
                                    Wc + (size_t)l * CC_DIM * D_DIM,
                                    pAtr, pAct, pInv);
        scan_kernel<<<TR_DIM, CC_DIM>>>(pAtr, pAct, pInv, start,
                                        a + (size_t)l * TR_DIM,
                                        b + (size_t)l * CC_DIM,
                                        state + (size_t)l * TR_DIM * CC_DIM,
                                        pScaled);
        sgemm_tn<<<dim3(D_DIM / BN, T_LEN / BM), 256>>>(
            pScaled, W0 + (size_t)l * D_DIM * F_DIM, pH, T_LEN, D_DIM, F_DIM);
        ln_leaky_kernel<<<T_LEN, 128>>>(pH, b0 + (size_t)l * D_DIM,
                                        g0 + (size_t)l * D_DIM,
                                        be0 + (size_t)l * D_DIM);
        sgemm_tn<<<dim3(D_DIM / BN, T_LEN / BM), 256>>>(
            pH, W1 + (size_t)l * D_DIM * D_DIM, pZ, T_LEN, D_DIM, D_DIM);
        ln_leaky_kernel<<<T_LEN, 128>>>(pZ, b1 + (size_t)l * D_DIM,
                                        g1 + (size_t)l * D_DIM,
                                        be1 + (size_t)l * D_DIM);
        if (l < L_NUM - 1)
            residual_kernel<<<512, 256>>>(pX, pZ, ND);
    }
    copy_kernel<<<512, 256>>>(out, pZ, ND);
}

// round 3
// speedup vs baseline: 1.3114x; 1.3114x over previous
#include <cuda_runtime.h>
#include <cuda_bf16.h>
#include <math.h>

#define T_LEN 4096
#define D_DIM 512
#define TR_DIM 64
#define CC_DIM 64
#define F_DIM 8192   // 2*TR*CC
#define L_NUM 3

// ------------------------- scratch (device globals; no alloc) ---------------
__device__ float g_X[(size_t)T_LEN * D_DIM];          // running residual x
__device__ float g_atr[(size_t)T_LEN * TR_DIM];       // |tr|
__device__ float g_act[(size_t)T_LEN * CC_DIM];       // |ct|
__device__ float g_inv[T_LEN];                        // 1/(1e-8 + S_tr*S_ct)
__device__ float g_scaled[(size_t)T_LEN * F_DIM];     // scan features (tf32-rounded)
__device__ float g_h[(size_t)T_LEN * D_DIM];          // hidden after GEMM0
__device__ float g_z[(size_t)T_LEN * D_DIM];          // layer output z
__device__ float g_W0t[(size_t)L_NUM * D_DIM * F_DIM]; // tf32-rounded W0
__device__ float g_W1t[(size_t)L_NUM * D_DIM * D_DIM]; // tf32-rounded W1

__device__ __forceinline__ float tf32r(float x) {
    float y;
    asm("cvt.rna.tf32.f32 %0, %1;" : "=f"(y) : "f"(x));
    return y;
}

__device__ __forceinline__ void cp_async16(void* smem_dst, const void* gsrc) {
    unsigned saddr = (unsigned)__cvta_generic_to_shared(smem_dst);
    asm volatile("cp.async.cg.shared.global [%0], [%1], 16;\n" :: "r"(saddr), "l"(gsrc));
}

// ------------------------- small utility kernels ----------------------------
__global__ void copy_kernel(float* __restrict__ dst, const float* __restrict__ src, int n) {
    int i = blockIdx.x * blockDim.x + threadIdx.x;
    int stride = gridDim.x * blockDim.x;
    for (; i < n; i += stride) dst[i] = src[i];
}

__global__ void residual_kernel(float* __restrict__ x, const float* __restrict__ z, int n) {
    int i = blockIdx.x * blockDim.x + threadIdx.x;
    int stride = gridDim.x * blockDim.x;
    for (; i < n; i += stride) x[i] += z[i];
}

__global__ void tf32_round_kernel(float* __restrict__ dst, const float* __restrict__ src, int n) {
    int i = blockIdx.x * blockDim.x + threadIdx.x;
    int stride = gridDim.x * blockDim.x;
    for (; i < n; i += stride) dst[i] = tf32r(src[i]);
}

// ------------------------- projections: |tr|, |ct|, inv-sum ------------------
__global__ __launch_bounds__(128) void proj_kernel(
    const float* __restrict__ X, const float* __restrict__ Wtr,
    const float* __restrict__ Wc, float* __restrict__ atr,
    float* __restrict__ act, float* __restrict__ inv)
{
    __shared__ float4 xs[D_DIM / 4];
    __shared__ float red[128];
    int t = blockIdx.x;
    int tid = threadIdx.x;

    const float4* xrow = (const float4*)(X + (size_t)t * D_DIM);
    xs[tid] = xrow[tid];
    __syncthreads();

    const float4* W = (tid < 64)
        ? (const float4*)(Wtr + (size_t)tid * D_DIM)
        : (const float4*)(Wc + (size_t)(tid - 64) * D_DIM);

    float s = 0.f;
#pragma unroll 8
    for (int k = 0; k < D_DIM / 4; ++k) {
        float4 w = W[k], x4 = xs[k];
        s += w.x * x4.x + w.y * x4.y + w.z * x4.z + w.w * x4.w;
    }
    float av = fabsf(s);
    if (tid < 64) atr[(size_t)t * TR_DIM + tid] = av;
    else          act[(size_t)t * CC_DIM + tid - 64] = av;

    red[tid] = av;
    __syncthreads();
#pragma unroll
    for (int off = 32; off > 0; off >>= 1) {
        if ((tid & 63) < off) red[tid] += red[tid + off];
        __syncthreads();
    }
    if (tid == 0) inv[t] = 1.f / (1e-8f + red[0] * red[64]);
}

// ------------------------- segmented complex scan + feature map -------------
// Output is tf32-rounded (feeds the tf32 GEMM0 directly).
__global__ __launch_bounds__(CC_DIM) void scan_kernel(
    const float* __restrict__ atr, const float* __restrict__ act,
    const float* __restrict__ inv, const unsigned int* __restrict__ start,
    const float* __restrict__ a, const float* __restrict__ b,
    const float* __restrict__ st0, float* __restrict__ scaled)
{
    int i = blockIdx.x;
    int j = threadIdx.x;
    float mag_d = expf(-fabsf(a[i]));
    float bj = b[j];
    float dr = mag_d * cosf(bj);
    float di = mag_d * sinf(bj);

    float sr = st0[i * CC_DIM + j];
    float si = 0.f;
    int c = i * CC_DIM + j;

#pragma unroll 4
    for (int t = 0; t < T_LEN; ++t) {
        float at = atr[(size_t)t * TR_DIM + i];
        float ac = act[(size_t)t * CC_DIM + j];
        float p = at * ac * inv[t];
        if (start[t] != 0u) { sr = 0.f; si = 0.f; }
        float nsr = sr * dr - si * di + p;
        float nsi = sr * di + si * dr;
        sr = nsr; si = nsi;
        float r = sqrtf(sr * sr + si * si);
        float f = (r > 1e-30f) ? (log1pf(r) / r) : 1.0f;
        scaled[(size_t)t * F_DIM + c]                   = tf32r(f * si);
        scaled[(size_t)t * F_DIM + (TR_DIM*CC_DIM) + c] = tf32r(f * sr);
    }
}

// ------------------------- TF32 tensor-core GEMM: C = A @ B^T ----------------
// A: MxK row-major (tf32-rounded fp32), B: NxK row-major (tf32-rounded fp32).
// 128x128x32 tiles, 8 warps (4m x 2n), warp tile 32x64, mma.m16n8k8.
#define GBM 128
#define GBN 128
#define GBK 32
#define ASTR 36   // padded smem row stride in words -> conflict-free fragment LDS

__global__ __launch_bounds__(256, 1) void sgemm_tf32(
    const float* __restrict__ A, const float* __restrict__ B,
    float* __restrict__ C, int M, int N, int K)
{
    extern __shared__ float sm[];
    float* Asb[2] = { sm,                 sm + GBM * ASTR };
    float* Bsb[2] = { sm + 2 * GBM * ASTR, sm + 2 * GBM * ASTR + GBN * ASTR };

    int tid = threadIdx.x;
    int bm = blockIdx.y * GBM, bn = blockIdx.x * GBN;
    int lane = tid & 31, wid = tid >> 5;
    int wm = wid & 3, wn = wid >> 2;
    int g = lane >> 2, c4 = lane & 3;

    float acc[2][8][4];
#pragma unroll
    for (int i = 0; i < 2; ++i)
#pragma unroll
        for (int f = 0; f < 8; ++f)
#pragma unroll
            for (int r = 0; r < 4; ++r) acc[i][f][r] = 0.f;

    int lrow = tid >> 3;     // 0..31
    int lq = tid & 7;        // 16B chunk within 128B row

    auto load_tiles = [&](int buf, int k0) {
        const float* Ag = A + (size_t)bm * K + k0;
        const float* Bg = B + (size_t)bn * K + k0;
        float* as = Asb[buf];
        float* bs = Bsb[buf];
#pragma unroll
        for (int p = 0; p < 4; ++p) {
            int r = lrow + p * 32;
            cp_async16(as + r * ASTR + lq * 4, Ag + (size_t)r * K + lq * 4);
        }
#pragma unroll
        for (int p = 0; p < 4; ++p) {
            int r = lrow + p * 32;
            cp_async16(bs + r * ASTR + lq * 4, Bg + (size_t)r * K + lq * 4);
        }
    };

    auto compute = [&](int buf) {
        const float* as = Asb[buf];
        const float* bs = Bsb[buf];
#pragma unroll
        for (int ks = 0; ks < 4; ++ks) {
            int kb = ks * 8;
            unsigned af[2][4];
            unsigned bf[8][2];
#pragma unroll
            for (int i = 0; i < 2; ++i) {
                int rb = wm * 32 + i * 16 + g;
                af[i][0] = __float_as_uint(as[(rb)     * ASTR + kb + c4]);
                af[i][1] = __float_as_uint(as[(rb + 8) * ASTR + kb + c4]);
                af[i][2] = __float_as_uint(as[(rb)     * ASTR + kb + c4 + 4]);
                af[i][3] = __float_as_uint(as[(rb + 8) * ASTR + kb + c4 + 4]);
            }
#pragma unroll
            for (int f = 0; f < 8; ++f) {
                int nb = wn * 64 + f * 8 + g;
                bf[f][0] = __float_as_uint(bs[nb * ASTR + kb + c4]);
                bf[f][1] = __float_as_uint(bs[nb * ASTR + kb + c4 + 4]);
            }
#pragma unroll
            for (int i = 0; i < 2; ++i)
#pragma unroll
                for (int f = 0; f < 8; ++f) {
                    asm volatile(
                        "mma.sync.aligned.m16n8k8.row.col.f32.tf32.tf32.f32 "
                        "{%0,%1,%2,%3}, {%4,%5,%6,%7}, {%8,%9}, {%0,%1,%2,%3};"
                        : "+f"(acc[i][f][0]), "+f"(acc[i][f][1]),
                          "+f"(acc[i][f][2]), "+f"(acc[i][f][3])
                        : "r"(af[i][0]), "r"(af[i][1]), "r"(af[i][2]), "r"(af[i][3]),
                          "r"(bf[f][0]), "r"(bf[f][1]));
                }
        }
    };

    int NK = K / GBK;
    load_tiles(0, 0);
    asm volatile("cp.async.commit_group;\n");
    asm volatile("cp.async.wait_group 0;\n");
    __syncthreads();

    for (int it = 0; it < NK; ++it) {
        int cur = it & 1;
        if (it + 1 < NK) {
            load_tiles(cur ^ 1, (it + 1) * GBK);
            asm volatile("cp.async.commit_group;\n");
        }
        compute(cur);
        if (it + 1 < NK) asm volatile("cp.async.wait_group 0;\n");
        __syncthreads();
    }

#pragma unroll
    for (int i = 0; i < 2; ++i) {
        int r0 = bm + wm * 32 + i * 16 + g;
#pragma unroll
        for (int f = 0; f < 8; ++f) {
            int col = bn + wn * 64 + f * 8 + 2 * c4;
            *(float2*)(C + (size_t)r0 * N + col) = make_float2(acc[i][f][0], acc[i][f][1]);
            *(float2*)(C + (size_t)(r0 + 8) * N + col) = make_float2(acc[i][f][2], acc[i][f][3]);
        }
    }
}

// ------------------------- layernorm + leaky_relu (in place) ----------------
// round_out != 0 -> output rounded to tf32 (feeds next tf32 GEMM)
__global__ __launch_bounds__(128) void ln_leaky_kernel(
    float* __restrict__ Z, const float* __restrict__ bias,
    const float* __restrict__ g, const float* __restrict__ beta, int round_out)
{
    __shared__ float sh[8];
    int t = blockIdx.x;
    int tid = threadIdx.x;
    float* row = Z + (size_t)t * D_DIM;

    float v[4];
    float s = 0.f;
#pragma unroll
    for (int q = 0; q < 4; ++q) {
        int idx = tid + q * 128;
        v[q] = row[idx] + bias[idx];
        s += v[q];
    }
#pragma unroll
    for (int off = 16; off > 0; off >>= 1) s += __shfl_xor_sync(0xffffffffu, s, off);
    if ((tid & 31) == 0) sh[tid >> 5] = s;
    __syncthreads();
    float mean = (sh[0] + sh[1] + sh[2] + sh[3]) * (1.f / D_DIM);

    float vs = 0.f;
#pragma unroll
    for (int q = 0; q < 4; ++q) { float d = v[q] - mean; vs += d * d; }
#pragma unroll
    for (int off = 16; off > 0; off >>= 1) vs += __shfl_xor_sync(0xffffffffu, vs, off);
    if ((tid & 31) == 0) sh[4 + (tid >> 5)] = vs;
    __syncthreads();
    float var = (sh[4] + sh[5] + sh[6] + sh[7]) * (1.f / D_DIM);
    float rstd = rsqrtf(var + 1e-5f);

#pragma unroll
    for (int q = 0; q < 4; ++q) {
        int idx = tid + q * 128;
        float y = (v[q] - mean) * rstd * g[idx] + beta[idx];
        y = (y > 0.f) ? y : 0.01f * y;
        row[idx] = round_out ? tf32r(y) : y;
    }
}

// ------------------------- launch ------------------------------------------
extern "C" void kernel_launch(void* const* d_in, const int* in_sizes, int n_in,
                              void* d_out, int out_size)
{
    const float* x     = (const float*)d_in[0];
    const float* state = (const float*)d_in[1];
    const unsigned int* start = (const unsigned int*)d_in[2];
    const float* Wtr   = (const float*)d_in[3];
    const float* Wc    = (const float*)d_in[4];
    const float* a     = (const float*)d_in[5];
    const float* b     = (const float*)d_in[6];
    const float* W0    = (const float*)d_in[7];
    const float* b0    = (const float*)d_in[8];
    const float* g0    = (const float*)d_in[9];
    const float* be0   = (const float*)d_in[10];
    const float* W1    = (const float*)d_in[11];
    const float* b1    = (const float*)d_in[12];
    const float* g1    = (const float*)d_in[13];
    const float* be1   = (const float*)d_in[14];
    float* out = (float*)d_out;

    float *pX, *pAtr, *pAct, *pInv, *pScaled, *pH, *pZ, *pW0t, *pW1t;
    cudaGetSymbolAddress((void**)&pX, g_X);
    cudaGetSymbolAddress((void**)&pAtr, g_atr);
    cudaGetSymbolAddress((void**)&pAct, g_act);
    cudaGetSymbolAddress((void**)&pInv, g_inv);
    cudaGetSymbolAddress((void**)&pScaled, g_scaled);
    cudaGetSymbolAddress((void**)&pH, g_h);
    cudaGetSymbolAddress((void**)&pZ, g_z);
    cudaGetSymbolAddress((void**)&pW0t, g_W0t);
    cudaGetSymbolAddress((void**)&pW1t, g_W1t);

    const int SMEM_GEMM = 2 * (GBM + GBN) * ASTR * (int)sizeof(float);  // 73728
    cudaFuncSetAttribute(sgemm_tf32, cudaFuncAttributeMaxDynamicSharedMemorySize, SMEM_GEMM);

    const int ND = T_LEN * D_DIM;
    copy_kernel<<<512, 256>>>(pX, x, ND);
    tf32_round_kernel<<<1024, 256>>>(pW0t, W0, L_NUM * D_DIM * F_DIM);
    tf32_round_kernel<<<256, 256>>>(pW1t, W1, L_NUM * D_DIM * D_DIM);

    dim3 ggrid(D_DIM / GBN, T_LEN / GBM);  // (4, 32)

    for (int l = 0; l < L_NUM; ++l) {
        proj_kernel<<<T_LEN, 128>>>(pX, Wtr + (size_t)l * TR_DIM * D_DIM,
                                    Wc + (size_t)l * CC_DIM * D_DIM,
                                    pAtr, pAct, pInv);
        scan_kernel<<<TR_DIM, CC_DIM>>>(pAtr, pAct, pInv, start,
                                        a + (size_t)l * TR_DIM,
                                        b + (size_t)l * CC_DIM,
                                        state + (size_t)l * TR_DIM * CC_DIM,
                                        pScaled);
        sgemm_tf32<<<ggrid, 256, SMEM_GEMM>>>(
            pScaled, pW0t + (size_t)l * D_DIM * F_DIM, pH, T_LEN, D_DIM, F_DIM);
        ln_leaky_kernel<<<T_LEN, 128>>>(pH, b0 + (size_t)l * D_DIM,
                                        g0 + (size_t)l * D_DIM,
                                        be0 + (size_t)l * D_DIM, 1);
        sgemm_tf32<<<ggrid, 256, SMEM_GEMM>>>(
            pH, pW1t + (size_t)l * D_DIM * D_DIM, pZ, T_LEN, D_DIM, D_DIM);
        ln_leaky_kernel<<<T_LEN, 128>>>(pZ, b1 + (size_t)l * D_DIM,
                                        g1 + (size_t)l * D_DIM,
                                        be1 + (size_t)l * D_DIM, 0);
        if (l < L_NUM - 1)
            residual_kernel<<<512, 256>>>(pX, pZ, ND);
    }
    copy_kernel<<<512, 256>>>(out, pZ, ND);
}

// round 4
// speedup vs baseline: 5.6018x; 4.2716x over previous
#include <cuda_runtime.h>
#include <cuda_bf16.h>
#include <math.h>

#define T_LEN 4096
#define D_DIM 512
#define TR_DIM 64
#define CC_DIM 64
#define F_DIM 8192   // 2*TR*CC
#define L_NUM 3
#define NCH 64       // scan chunks
#define CHUNK 64     // timesteps per chunk (NCH*CHUNK = T_LEN)
#define NCHAN (TR_DIM * CC_DIM)

// ------------------------- scratch (device globals; no alloc) ---------------
__device__ float g_X[(size_t)T_LEN * D_DIM];
__device__ float g_atr[(size_t)T_LEN * TR_DIM];
__device__ float g_act[(size_t)T_LEN * CC_DIM];
__device__ float g_inv[T_LEN];
__device__ float g_scaled[(size_t)T_LEN * F_DIM];
__device__ float g_h[(size_t)T_LEN * D_DIM];
__device__ float g_z[(size_t)T_LEN * D_DIM];
__device__ float g_W0t[(size_t)L_NUM * D_DIM * F_DIM];
__device__ float g_W1t[(size_t)L_NUM * D_DIM * D_DIM];
// scan chunk scratch: [NCH][NCHAN]
__device__ float g_cAr[(size_t)NCH * NCHAN];
__device__ float g_cAi[(size_t)NCH * NCHAN];
__device__ float g_cBr[(size_t)NCH * NCHAN];
__device__ float g_cBi[(size_t)NCH * NCHAN];
__device__ float g_sinr[(size_t)NCH * NCHAN];
__device__ float g_sini[(size_t)NCH * NCHAN];

__device__ __forceinline__ float tf32r(float x) {
    float y;
    asm("cvt.rna.tf32.f32 %0, %1;" : "=f"(y) : "f"(x));
    return y;
}

__device__ __forceinline__ void cp_async16(void* smem_dst, const void* gsrc) {
    unsigned saddr = (unsigned)__cvta_generic_to_shared(smem_dst);
    asm volatile("cp.async.cg.shared.global [%0], [%1], 16;\n" :: "r"(saddr), "l"(gsrc));
}

// ------------------------- small utility kernels ----------------------------
__global__ void copy_kernel(float* __restrict__ dst, const float* __restrict__ src, int n) {
    int i = blockIdx.x * blockDim.x + threadIdx.x;
    int stride = gridDim.x * blockDim.x;
    for (; i < n; i += stride) dst[i] = src[i];
}

__global__ void residual_kernel(float* __restrict__ x, const float* __restrict__ z, int n) {
    int i = blockIdx.x * blockDim.x + threadIdx.x;
    int stride = gridDim.x * blockDim.x;
    for (; i < n; i += stride) x[i] += z[i];
}

__global__ void tf32_round_kernel(float* __restrict__ dst, const float* __restrict__ src, int n) {
    int i = blockIdx.x * blockDim.x + threadIdx.x;
    int stride = gridDim.x * blockDim.x;
    for (; i < n; i += stride) dst[i] = tf32r(src[i]);
}

// ------------------------- fused projection GEMM ----------------------------
// One block: 128 tokens x 128 outputs (64 tr + 64 ct), K = 512.
// Writes |tr|, |ct| and per-token inv-sum. Grid = 32 blocks, 256 threads.
#define PBM 128
#define PBK 16
__global__ __launch_bounds__(256) void proj_gemm_kernel(
    const float* __restrict__ X, const float* __restrict__ Wtr,
    const float* __restrict__ Wc, float* __restrict__ atr,
    float* __restrict__ act, float* __restrict__ inv)
{
    __shared__ float Xs[PBK][PBM + 4];
    __shared__ float Ws[PBK][PBM + 4];
    __shared__ float red[PBM][2];

    int tid = threadIdx.x;
    int bm = blockIdx.x * PBM;
    int tx = tid & 15;    // output dir: 8 cols each
    int ty = tid >> 4;    // token dir:  8 rows each

    // zero reduction buffer
    if (tid < 128) { red[tid][0] = 0.f; red[tid][1] = 0.f; }

    float acc[8][8];
#pragma unroll
    for (int i = 0; i < 8; ++i)
#pragma unroll
        for (int j = 0; j < 8; ++j) acc[i][j] = 0.f;

    for (int k0 = 0; k0 < D_DIM; k0 += PBK) {
        // load X tile 128x16 (512 float4, 2 per thread), transposed into smem
#pragma unroll
        for (int r = 0; r < 2; ++r) {
            int idx = tid + r * 256;
            int row = idx >> 2, c4 = idx & 3;
            float4 v = *(const float4*)(X + (size_t)(bm + row) * D_DIM + k0 + c4 * 4);
            Xs[c4 * 4 + 0][row] = v.x;
            Xs[c4 * 4 + 1][row] = v.y;
            Xs[c4 * 4 + 2][row] = v.z;
            Xs[c4 * 4 + 3][row] = v.w;
        }
        // load W tile 128x16 (rows 0..63 from Wtr, 64..127 from Wc)
#pragma unroll
        for (int r = 0; r < 2; ++r) {
            int idx = tid + r * 256;
            int row = idx >> 2, c4 = idx & 3;
            const float* Wrow = (row < 64) ? (Wtr + (size_t)row * D_DIM)
                                           : (Wc + (size_t)(row - 64) * D_DIM);
            float4 v = *(const float4*)(Wrow + k0 + c4 * 4);
            Ws[c4 * 4 + 0][row] = v.x;
            Ws[c4 * 4 + 1][row] = v.y;
            Ws[c4 * 4 + 2][row] = v.z;
            Ws[c4 * 4 + 3][row] = v.w;
        }
        __syncthreads();

#pragma unroll
        for (int kk = 0; kk < PBK; ++kk) {
            float xv[8], wv[8];
#pragma unroll
            for (int i = 0; i < 8; ++i) xv[i] = Xs[kk][ty * 8 + i];
#pragma unroll
            for (int j = 0; j < 8; ++j) wv[j] = Ws[kk][tx * 8 + j];
#pragma unroll
            for (int i = 0; i < 8; ++i)
#pragma unroll
                for (int j = 0; j < 8; ++j) acc[i][j] += xv[i] * wv[j];
        }
        __syncthreads();
    }

    // abs + write + partial sums (each thread's 8 outputs are entirely in one half)
    int half = (tx >= 8);   // 0 = tr, 1 = ct
#pragma unroll
    for (int i = 0; i < 8; ++i) {
        int tok = ty * 8 + i;
        float psum = 0.f;
#pragma unroll
        for (int j = 0; j < 8; ++j) {
            float av = fabsf(acc[i][j]);
            acc[i][j] = av;
            psum += av;
            int o = tx * 8 + j;
            if (o < 64) atr[(size_t)(bm + tok) * TR_DIM + o] = av;
            else        act[(size_t)(bm + tok) * CC_DIM + o - 64] = av;
        }
        atomicAdd(&red[tok][half], psum);
    }
    __syncthreads();
    if (tid < 128)
        inv[bm + tid] = 1.f / (1e-8f + red[tid][0] * red[tid][1]);
}

// ------------------------- scan pass A: chunk (A,B) --------------------------
// grid (TR, NCH), block CC. s_t = (start? 0 : d*s_{t-1}) + p_t within chunk,
// starting from 0; A = prod of (start? 0 : d).
__global__ __launch_bounds__(CC_DIM) void scan_chunkA_kernel(
    const float* __restrict__ atr, const float* __restrict__ act,
    const float* __restrict__ inv, const unsigned int* __restrict__ start,
    const float* __restrict__ a, const float* __restrict__ b)
{
    int i = blockIdx.x;
    int cidx = blockIdx.y;
    int j = threadIdx.x;
    float mag_d = expf(-fabsf(a[i]));
    float bj = b[j];
    float dr = mag_d * cosf(bj);
    float di = mag_d * sinf(bj);

    float sr = 0.f, si = 0.f;
    float ar = 1.f, ai = 0.f;
    int t0 = cidx * CHUNK;

#pragma unroll 4
    for (int tt = 0; tt < CHUNK; ++tt) {
        int t = t0 + tt;
        float at = atr[(size_t)t * TR_DIM + i];
        float ac = act[(size_t)t * CC_DIM + j];
        float p = at * ac * inv[t];
        if (start[t] != 0u) { sr = 0.f; si = 0.f; ar = 0.f; ai = 0.f; }
        float nsr = sr * dr - si * di + p;
        float nsi = sr * di + si * dr;
        sr = nsr; si = nsi;
        float nar = ar * dr - ai * di;
        float nai = ar * di + ai * dr;
        ar = nar; ai = nai;
    }
    int ch = i * CC_DIM + j;
    size_t o = (size_t)cidx * NCHAN + ch;
    g_cAr[o] = ar; g_cAi[o] = ai;
    g_cBr[o] = sr; g_cBi[o] = si;
}

// ------------------------- scan pass B: combine chunks -----------------------
// 4096 threads; sequential over NCH chunks. Stores incoming state per chunk.
__global__ __launch_bounds__(256) void scan_combine_kernel(const float* __restrict__ st0)
{
    int ch = blockIdx.x * blockDim.x + threadIdx.x;
    if (ch >= NCHAN) return;
    float sr = st0[ch];
    float si = 0.f;
    for (int c = 0; c < NCH; ++c) {
        size_t o = (size_t)c * NCHAN + ch;
        g_sinr[o] = sr; g_sini[o] = si;
        float ar = g_cAr[o], ai = g_cAi[o];
        float nsr = sr * ar - si * ai + g_cBr[o];
        float nsi = sr * ai + si * ar + g_cBi[o];
        sr = nsr; si = nsi;
    }
}

// ------------------------- scan pass C: rescan + features --------------------
__global__ __launch_bounds__(CC_DIM) void scan_chunkC_kernel(
    const float* __restrict__ atr, const float* __restrict__ act,
    const float* __restrict__ inv, const unsigned int* __restrict__ start,
    const float* __restrict__ a, const float* __restrict__ b,
    float* __restrict__ scaled)
{
    int i = blockIdx.x;
    int cidx = blockIdx.y;
    int j = threadIdx.x;
    float mag_d = expf(-fabsf(a[i]));
    float bj = b[j];
    float dr = mag_d * cosf(bj);
    float di = mag_d * sinf(bj);

    int ch = i * CC_DIM + j;
    size_t o = (size_t)cidx * NCHAN + ch;
    float sr = g_sinr[o], si = g_sini[o];
    int t0 = cidx * CHUNK;

#pragma unroll 4
    for (int tt = 0; tt < CHUNK; ++tt) {
        int t = t0 + tt;
        float at = atr[(size_t)t * TR_DIM + i];
        float ac = act[(size_t)t * CC_DIM + j];
        float p = at * ac * inv[t];
        if (start[t] != 0u) { sr = 0.f; si = 0.f; }
        float nsr = sr * dr - si * di + p;
        float nsi = sr * di + si * dr;
        sr = nsr; si = nsi;
        float r = sqrtf(sr * sr + si * si);
        float f = (r > 1e-30f) ? (log1pf(r) / r) : 1.0f;
        scaled[(size_t)t * F_DIM + ch]                      = tf32r(f * si);
        scaled[(size_t)t * F_DIM + (TR_DIM * CC_DIM) + ch]  = tf32r(f * sr);
    }
}

// ------------------------- TF32 tensor-core GEMM: C = A @ B^T ----------------
#define GBM 128
#define GBN 128
#define GBK 32
#define ASTR 36

__global__ __launch_bounds__(256, 1) void sgemm_tf32(
    const float* __restrict__ A, const float* __restrict__ B,
    float* __restrict__ C, int M, int N, int K)
{
    extern __shared__ float sm[];
    float* Asb[2] = { sm,                  sm + GBM * ASTR };
    float* Bsb[2] = { sm + 2 * GBM * ASTR, sm + 2 * GBM * ASTR + GBN * ASTR };

    int tid = threadIdx.x;
    int bm = blockIdx.y * GBM, bn = blockIdx.x * GBN;
    int lane = tid & 31, wid = tid >> 5;
    int wm = wid & 3, wn = wid >> 2;
    int g = lane >> 2, c4 = lane & 3;

    float acc[2][8][4];
#pragma unroll
    for (int i = 0; i < 2; ++i)
#pragma unroll
        for (int f = 0; f < 8; ++f)
#pragma unroll
            for (int r = 0; r < 4; ++r) acc[i][f][r] = 0.f;

    int lrow = tid >> 3;
    int lq = tid & 7;

    auto load_tiles = [&](int buf, int k0) {
        const float* Ag = A + (size_t)bm * K + k0;
        const float* Bg = B + (size_t)bn * K + k0;
        float* as = Asb[buf];
        float* bs = Bsb[buf];
#pragma unroll
        for (int p = 0; p < 4; ++p) {
            int r = lrow + p * 32;
            cp_async16(as + r * ASTR + lq * 4, Ag + (size_t)r * K + lq * 4);
        }
#pragma unroll
        for (int p = 0; p < 4; ++p) {
            int r = lrow + p * 32;
            cp_async16(bs + r * ASTR + lq * 4, Bg + (size_t)r * K + lq * 4);
        }
    };

    auto compute = [&](int buf) {
        const float* as = Asb[buf];
        const float* bs = Bsb[buf];
#pragma unroll
        for (int ks = 0; ks < 4; ++ks) {
            int kb = ks * 8;
            unsigned af[2][4];
            unsigned bf[8][2];
#pragma unroll
            for (int i = 0; i < 2; ++i) {
                int rb = wm * 32 + i * 16 + g;
                af[i][0] = __float_as_uint(as[(rb)     * ASTR + kb + c4]);
                af[i][1] = __float_as_uint(as[(rb + 8) * ASTR + kb + c4]);
                af[i][2] = __float_as_uint(as[(rb)     * ASTR + kb + c4 + 4]);
                af[i][3] = __float_as_uint(as[(rb + 8) * ASTR + kb + c4 + 4]);
            }
#pragma unroll
            for (int f = 0; f < 8; ++f) {
                int nb = wn * 64 + f * 8 + g;
                bf[f][0] = __float_as_uint(bs[nb * ASTR + kb + c4]);
                bf[f][1] = __float_as_uint(bs[nb * ASTR + kb + c4 + 4]);
            }
#pragma unroll
            for (int i = 0; i < 2; ++i)
#pragma unroll
                for (int f = 0; f < 8; ++f) {
                    asm volatile(
                        "mma.sync.aligned.m16n8k8.row.col.f32.tf32.tf32.f32 "
                        "{%0,%1,%2,%3}, {%4,%5,%6,%7}, {%8,%9}, {%0,%1,%2,%3};"
                        : "+f"(acc[i][f][0]), "+f"(acc[i][f][1]),
                          "+f"(acc[i][f][2]), "+f"(acc[i][f][3])
                        : "r"(af[i][0]), "r"(af[i][1]), "r"(af[i][2]), "r"(af[i][3]),
                          "r"(bf[f][0]), "r"(bf[f][1]));
                }
        }
    };

    int NK = K / GBK;
    load_tiles(0, 0);
    asm volatile("cp.async.commit_group;\n");
    asm volatile("cp.async.wait_group 0;\n");
    __syncthreads();

    for (int it = 0; it < NK; ++it) {
        int cur = it & 1;
        if (it + 1 < NK) {
            load_tiles(cur ^ 1, (it + 1) * GBK);
            asm volatile("cp.async.commit_group;\n");
        }
        compute(cur);
        if (it + 1 < NK) asm volatile("cp.async.wait_group 0;\n");
        __syncthreads();
    }

#pragma unroll
    for (int i = 0; i < 2; ++i) {
        int r0 = bm + wm * 32 + i * 16 + g;
#pragma unroll
        for (int f = 0; f < 8; ++f) {
            int col = bn + wn * 64 + f * 8 + 2 * c4;
            *(float2*)(C + (size_t)r0 * N + col) = make_float2(acc[i][f][0], acc[i][f][1]);
            *(float2*)(C + (size_t)(r0 + 8) * N + col) = make_float2(acc[i][f][2], acc[i][f][3]);
        }
    }
}

// ------------------------- layernorm + leaky_relu (in place) ----------------
__global__ __launch_bounds__(128) void ln_leaky_kernel(
    float* __restrict__ Z, const float* __restrict__ bias,
    const float* __restrict__ g, const float* __restrict__ beta, int round_out)
{
    __shared__ float sh[8];
    int t = blockIdx.x;
    int tid = threadIdx.x;
    float* row = Z + (size_t)t * D_DIM;

    float v[4];
    float s = 0.f;
#pragma unroll
    for (int q = 0; q < 4; ++q) {
        int idx = tid + q * 128;
        v[q] = row[idx] + bias[idx];
        s += v[q];
    }
#pragma unroll
    for (int off = 16; off > 0; off >>= 1) s += __shfl_xor_sync(0xffffffffu, s, off);
    if ((tid & 31) == 0) sh[tid >> 5] = s;
    __syncthreads();
    float mean = (sh[0] + sh[1] + sh[2] + sh[3]) * (1.f / D_DIM);

    float vs = 0.f;
#pragma unroll
    for (int q = 0; q < 4; ++q) { float d = v[q] - mean; vs += d * d; }
#pragma unroll
    for (int off = 16; off > 0; off >>= 1) vs += __shfl_xor_sync(0xffffffffu, vs, off);
    if ((tid & 31) == 0) sh[4 + (tid >> 5)] = vs;
    __syncthreads();
    float var = (sh[4] + sh[5] + sh[6] + sh[7]) * (1.f / D_DIM);
    float rstd = rsqrtf(var + 1e-5f);

#pragma unroll
    for (int q = 0; q < 4; ++q) {
        int idx = tid + q * 128;
        float y = (v[q] - mean) * rstd * g[idx] + beta[idx];
        y = (y > 0.f) ? y : 0.01f * y;
        row[idx] = round_out ? tf32r(y) : y;
    }
}

// ------------------------- launch ------------------------------------------
extern "C" void kernel_launch(void* const* d_in, const int* in_sizes, int n_in,
                              void* d_out, int out_size)
{
    const float* x     = (const float*)d_in[0];
    const float* state = (const float*)d_in[1];
    const unsigned int* start = (const unsigned int*)d_in[2];
    const float* Wtr   = (const float*)d_in[3];
    const float* Wc    = (const float*)d_in[4];
    const float* a     = (const float*)d_in[5];
    const float* b     = (const float*)d_in[6];
    const float* W0    = (const float*)d_in[7];
    const float* b0    = (const float*)d_in[8];
    const float* g0    = (const float*)d_in[9];
    const float* be0   = (const float*)d_in[10];
    const float* W1    = (const float*)d_in[11];
    const float* b1    = (const float*)d_in[12];
    const float* g1    = (const float*)d_in[13];
    const float* be1   = (const float*)d_in[14];
    float* out = (float*)d_out;

    float *pX, *pAtr, *pAct, *pInv, *pScaled, *pH, *pZ, *pW0t, *pW1t;
    cudaGetSymbolAddress((void**)&pX, g_X);
    cudaGetSymbolAddress((void**)&pAtr, g_atr);
    cudaGetSymbolAddress((void**)&pAct, g_act);
    cudaGetSymbolAddress((void**)&pInv, g_inv);
    cudaGetSymbolAddress((void**)&pScaled, g_scaled);
    cudaGetSymbolAddress((void**)&pH, g_h);
    cudaGetSymbolAddress((void**)&pZ, g_z);
    cudaGetSymbolAddress((void**)&pW0t, g_W0t);
    cudaGetSymbolAddress((void**)&pW1t, g_W1t);

    const int SMEM_GEMM = 2 * (GBM + GBN) * ASTR * (int)sizeof(float);  // 73728
    cudaFuncSetAttribute(sgemm_tf32, cudaFuncAttributeMaxDynamicSharedMemorySize, SMEM_GEMM);

    const int ND = T_LEN * D_DIM;
    copy_kernel<<<512, 256>>>(pX, x, ND);
    tf32_round_kernel<<<1024, 256>>>(pW0t, W0, L_NUM * D_DIM * F_DIM);
    tf32_round_kernel<<<256, 256>>>(pW1t, W1, L_NUM * D_DIM * D_DIM);

    dim3 ggrid(D_DIM / GBN, T_LEN / GBM);   // (4, 32)
    dim3 sgrid(TR_DIM, NCH);                // (64, 64)

    for (int l = 0; l < L_NUM; ++l) {
        proj_gemm_kernel<<<T_LEN / PBM, 256>>>(
            pX, Wtr + (size_t)l * TR_DIM * D_DIM,
            Wc + (size_t)l * CC_DIM * D_DIM, pAtr, pAct, pInv);
        scan_chunkA_kernel<<<sgrid, CC_DIM>>>(
            pAtr, pAct, pInv, start,
            a + (size_t)l * TR_DIM, b + (size_t)l * CC_DIM);
        scan_combine_kernel<<<NCHAN / 256, 256>>>(
            state + (size_t)l * TR_DIM * CC_DIM);
        scan_chunkC_kernel<<<sgrid, CC_DIM>>>(
            pAtr, pAct, pInv, start,
            a + (size_t)l * TR_DIM, b + (size_t)l * CC_DIM, pScaled);
        sgemm_tf32<<<ggrid, 256, SMEM_GEMM>>>(
            pScaled, pW0t + (size_t)l * D_DIM * F_DIM, pH, T_LEN, D_DIM, F_DIM);
        ln_leaky_kernel<<<T_LEN, 128>>>(pH, b0 + (size_t)l * D_DIM,
                                        g0 + (size_t)l * D_DIM,
                                        be0 + (size_t)l * D_DIM, 1);
        sgemm_tf32<<<ggrid, 256, SMEM_GEMM>>>(
            pH, pW1t + (size_t)l * D_DIM * D_DIM, pZ, T_LEN, D_DIM, D_DIM);
        ln_leaky_kernel<<<T_LEN, 128>>>(pZ, b1 + (size_t)l * D_DIM,
                                        g1 + (size_t)l * D_DIM,
                                        be1 + (size_t)l * D_DIM, 0);
        if (l < L_NUM - 1)
            residual_kernel<<<512, 256>>>(pX, pZ, ND);
    }
    copy_kernel<<<512, 256>>>(out, pZ, ND);
}

// round 5
// speedup vs baseline: 6.9413x; 1.2391x over previous
#include <cuda_runtime.h>
#include <cuda_bf16.h>
#include <math.h>

#define T_LEN 4096
#define D_DIM 512
#define TR_DIM 64
#define CC_DIM 64
#define F_DIM 8192   // 2*TR*CC
#define L_NUM 3
#define NCH 64       // scan chunks
#define CHUNK 64     // timesteps per chunk
#define NCHAN (TR_DIM * CC_DIM)

// ------------------------- scratch (device globals; no alloc) ---------------
__device__ float g_X[(size_t)T_LEN * D_DIM];
__device__ float g_atr[(size_t)T_LEN * TR_DIM];
__device__ float g_act[(size_t)T_LEN * CC_DIM];
__device__ float g_inv[T_LEN];
__device__ float g_scaled[(size_t)T_LEN * F_DIM];
__device__ float g_h[(size_t)T_LEN * D_DIM];
__device__ float g_z[(size_t)T_LEN * D_DIM];
__device__ float g_W0t[(size_t)L_NUM * D_DIM * F_DIM];
__device__ float g_W1t[(size_t)L_NUM * D_DIM * D_DIM];
__device__ float g_cAr[(size_t)NCH * NCHAN];
__device__ float g_cAi[(size_t)NCH * NCHAN];
__device__ float g_cBr[(size_t)NCH * NCHAN];
__device__ float g_cBi[(size_t)NCH * NCHAN];
__device__ float g_sinr[(size_t)NCH * NCHAN];
__device__ float g_sini[(size_t)NCH * NCHAN];

__device__ __forceinline__ float tf32r(float x) {
    float y;
    asm("cvt.rna.tf32.f32 %0, %1;" : "=f"(y) : "f"(x));
    return y;
}

__device__ __forceinline__ void cp_async16(void* smem_dst, const void* gsrc) {
    unsigned saddr = (unsigned)__cvta_generic_to_shared(smem_dst);
    asm volatile("cp.async.cg.shared.global [%0], [%1], 16;\n" :: "r"(saddr), "l"(gsrc));
}

// ------------------------- small utility kernels ----------------------------
__global__ void copy_kernel(float* __restrict__ dst, const float* __restrict__ src, int n) {
    int i = blockIdx.x * blockDim.x + threadIdx.x;
    int stride = gridDim.x * blockDim.x;
    for (; i < n; i += stride) dst[i] = src[i];
}

__global__ void tf32_round_kernel(float* __restrict__ dst, const float* __restrict__ src, int n) {
    int i = blockIdx.x * blockDim.x + threadIdx.x;
    int stride = gridDim.x * blockDim.x;
    for (; i < n; i += stride) dst[i] = tf32r(src[i]);
}

// ------------------------- fused projection GEMM ----------------------------
// Block: 32 tokens x 128 outputs (64 tr + 64 ct), K=512. Grid = 128 blocks.
#define PBM 32
#define PBK 32
__global__ __launch_bounds__(256) void proj_gemm_kernel(
    const float* __restrict__ X, const float* __restrict__ Wtr,
    const float* __restrict__ Wc, float* __restrict__ atr,
    float* __restrict__ act, float* __restrict__ inv)
{
    __shared__ float Xs[PBK][PBM + 4];
    __shared__ float Ws[PBK][128 + 4];
    __shared__ float red[PBM][2];

    int tid = threadIdx.x;
    int bm = blockIdx.x * PBM;
    int tx = tid & 31;    // output dir: 4 each
    int ty = tid >> 5;    // token dir:  4 each

    if (tid < 64) red[tid >> 1][tid & 1] = 0.f;

    float acc[4][4];
#pragma unroll
    for (int i = 0; i < 4; ++i)
#pragma unroll
        for (int j = 0; j < 4; ++j) acc[i][j] = 0.f;

    int lr = tid >> 3;   // 0..31
    int c4 = tid & 7;    // 0..7

    for (int k0 = 0; k0 < D_DIM; k0 += PBK) {
        // X tile 32x32: 256 float4, 1 per thread
        {
            float4 v = *(const float4*)(X + (size_t)(bm + lr) * D_DIM + k0 + c4 * 4);
            Xs[c4 * 4 + 0][lr] = v.x;
            Xs[c4 * 4 + 1][lr] = v.y;
            Xs[c4 * 4 + 2][lr] = v.z;
            Xs[c4 * 4 + 3][lr] = v.w;
        }
        // W tile 128x32: 1024 float4, 4 per thread
#pragma unroll
        for (int p = 0; p < 4; ++p) {
            int row = lr + p * 32;
            const float* Wrow = (row < 64) ? (Wtr + (size_t)row * D_DIM)
                                           : (Wc + (size_t)(row - 64) * D_DIM);
            float4 v = *(const float4*)(Wrow + k0 + c4 * 4);
            Ws[c4 * 4 + 0][row] = v.x;
            Ws[c4 * 4 + 1][row] = v.y;
            Ws[c4 * 4 + 2][row] = v.z;
            Ws[c4 * 4 + 3][row] = v.w;
        }
        __syncthreads();

#pragma unroll
        for (int kk = 0; kk < PBK; ++kk) {
            float xv[4], wv[4];
#pragma unroll
            for (int i = 0; i < 4; ++i) xv[i] = Xs[kk][ty * 4 + i];
#pragma unroll
            for (int j = 0; j < 4; ++j) wv[j] = Ws[kk][tx * 4 + j];
#pragma unroll
            for (int i = 0; i < 4; ++i)
#pragma unroll
                for (int j = 0; j < 4; ++j) acc[i][j] += xv[i] * wv[j];
        }
        __syncthreads();
    }

    int half = (tx >= 16);
#pragma unroll
    for (int i = 0; i < 4; ++i) {
        int tok = ty * 4 + i;
        float psum = 0.f;
#pragma unroll
        for (int j = 0; j < 4; ++j) {
            float av = fabsf(acc[i][j]);
            psum += av;
            int o = tx * 4 + j;
            if (o < 64) atr[(size_t)(bm + tok) * TR_DIM + o] = av;
            else        act[(size_t)(bm + tok) * CC_DIM + o - 64] = av;
        }
        atomicAdd(&red[tok][half], psum);
    }
    __syncthreads();
    if (tid < 32)
        inv[bm + tid] = 1.f / (1e-8f + red[tid][0] * red[tid][1]);
}

// ------------------------- scan pass A: chunk (A,B) --------------------------
// 1-warp block, thread handles channels (i, tid) and (i, tid+32).
// A = anystart ? 0 : d^CHUNK (closed form); B = local scan from zero.
__global__ __launch_bounds__(32) void scan_chunkA_kernel(
    const float* __restrict__ atr, const float* __restrict__ act,
    const float* __restrict__ inv, const unsigned int* __restrict__ start,
    const float* __restrict__ a, const float* __restrict__ b)
{
    __shared__ float ativ[CHUNK];
    __shared__ unsigned sfl[CHUNK];
    int i = blockIdx.x;
    int cidx = blockIdx.y;
    int tid = threadIdx.x;
    int t0 = cidx * CHUNK;

#pragma unroll
    for (int q = 0; q < 2; ++q) {
        int idx = tid + q * 32;
        int t = t0 + idx;
        ativ[idx] = atr[(size_t)t * TR_DIM + i] * inv[t];
        sfl[idx] = start[t];
    }
    __syncwarp();

    float mag = expf(-fabsf(a[i]));
    int j0 = tid, j1 = tid + 32;
    float b0 = b[j0], b1 = b[j1];
    float dr0 = mag * cosf(b0), di0 = mag * sinf(b0);
    float dr1 = mag * cosf(b1), di1 = mag * sinf(b1);

    // d^64 by repeated squaring
    float pr0 = dr0, pi0 = di0, pr1 = dr1, pi1 = di1;
#pragma unroll
    for (int q = 0; q < 6; ++q) {
        float n0r = pr0 * pr0 - pi0 * pi0, n0i = 2.f * pr0 * pi0;
        float n1r = pr1 * pr1 - pi1 * pi1, n1i = 2.f * pr1 * pi1;
        pr0 = n0r; pi0 = n0i; pr1 = n1r; pi1 = n1i;
    }

    float sr0 = 0.f, si0 = 0.f, sr1 = 0.f, si1 = 0.f;
    unsigned any = 0;

#pragma unroll 4
    for (int tt = 0; tt < CHUNK; ++tt) {
        float av = ativ[tt];
        unsigned st = sfl[tt];
        any |= st;
        const float* acp = act + (size_t)(t0 + tt) * CC_DIM;
        float p0 = av * acp[j0];
        float p1 = av * acp[j1];
        if (st) { sr0 = 0.f; si0 = 0.f; sr1 = 0.f; si1 = 0.f; }
        float n0r = sr0 * dr0 - si0 * di0 + p0;
        float n0i = sr0 * di0 + si0 * dr0;
        float n1r = sr1 * dr1 - si1 * di1 + p1;
        float n1i = sr1 * di1 + si1 * dr1;
        sr0 = n0r; si0 = n0i; sr1 = n1r; si1 = n1i;
    }

    size_t o0 = (size_t)cidx * NCHAN + i * CC_DIM + j0;
    size_t o1 = o0 + 32;
    float am = any ? 0.f : 1.f;
    g_cAr[o0] = am * pr0; g_cAi[o0] = am * pi0;
    g_cAr[o1] = am * pr1; g_cAi[o1] = am * pi1;
    g_cBr[o0] = sr0; g_cBi[o0] = si0;
    g_cBr[o1] = sr1; g_cBi[o1] = si1;
}

// ------------------------- scan pass B: combine chunks -----------------------
__global__ __launch_bounds__(256) void scan_combine_kernel(const float* __restrict__ st0)
{
    int ch = blockIdx.x * blockDim.x + threadIdx.x;
    if (ch >= NCHAN) return;
    float sr = st0[ch];
    float si = 0.f;
    for (int c = 0; c < NCH; ++c) {
        size_t o = (size_t)c * NCHAN + ch;
        g_sinr[o] = sr; g_sini[o] = si;
        float ar = g_cAr[o], ai = g_cAi[o];
        float nsr = sr * ar - si * ai + g_cBr[o];
        float nsi = sr * ai + si * ar + g_cBi[o];
        sr = nsr; si = nsi;
    }
}

// ------------------------- scan pass C: rescan + features --------------------
__device__ __forceinline__ float featf(float sr, float si) {
    // f = log1p(r)/r with r = |s|; fast-math variants, error << tf32 rounding
    float r2 = fmaxf(sr * sr + si * si, 1e-34f);
    float rr = rsqrtf(r2);       // 1/r
    float r = r2 * rr;           // r
    float flog = __logf(1.f + r) * rr;
    float fpoly = 1.f - r * (0.5f - r * (1.f / 3.f));
    return (r < 0.03f) ? fpoly : flog;
}

__global__ __launch_bounds__(32) void scan_chunkC_kernel(
    const float* __restrict__ atr, const float* __restrict__ act,
    const float* __restrict__ inv, const unsigned int* __restrict__ start,
    const float* __restrict__ a, const float* __restrict__ b,
    float* __restrict__ scaled)
{
    __shared__ float ativ[CHUNK];
    __shared__ unsigned sfl[CHUNK];
    int i = blockIdx.x;
    int cidx = blockIdx.y;
    int tid = threadIdx.x;
    int t0 = cidx * CHUNK;

#pragma unroll
    for (int q = 0; q < 2; ++q) {
        int idx = tid + q * 32;
        int t = t0 + idx;
        ativ[idx] = atr[(size_t)t * TR_DIM + i] * inv[t];
        sfl[idx] = start[t];
    }
    __syncwarp();

    float mag = expf(-fabsf(a[i]));
    int j0 = tid, j1 = tid + 32;
    float b0 = b[j0], b1 = b[j1];
    float dr0 = mag * cosf(b0), di0 = mag * sinf(b0);
    float dr1 = mag * cosf(b1), di1 = mag * sinf(b1);

    int ch0 = i * CC_DIM + j0;
    size_t o0 = (size_t)cidx * NCHAN + ch0;
    float sr0 = g_sinr[o0], si0 = g_sini[o0];
    float sr1 = g_sinr[o0 + 32], si1 = g_sini[o0 + 32];

#pragma unroll 2
    for (int tt = 0; tt < CHUNK; ++tt) {
        int t = t0 + tt;
        float av = ativ[tt];
        unsigned st = sfl[tt];
        const float* acp = act + (size_t)t * CC_DIM;
        float p0 = av * acp[j0];
        float p1 = av * acp[j1];
        if (st) { sr0 = 0.f; si0 = 0.f; sr1 = 0.f; si1 = 0.f; }
        float n0r = sr0 * dr0 - si0 * di0 + p0;
        float n0i = sr0 * di0 + si0 * dr0;
        float n1r = sr1 * dr1 - si1 * di1 + p1;
        float n1i = sr1 * di1 + si1 * dr1;
        sr0 = n0r; si0 = n0i; sr1 = n1r; si1 = n1i;

        float f0 = featf(sr0, si0);
        float f1 = featf(sr1, si1);
        float* row = scaled + (size_t)t * F_DIM;
        row[ch0]                      = tf32r(f0 * si0);
        row[ch0 + 32]                 = tf32r(f1 * si1);
        row[ch0 + NCHAN]              = tf32r(f0 * sr0);
        row[ch0 + 32 + NCHAN]         = tf32r(f1 * sr1);
    }
}

// ------------------------- TF32 tensor-core GEMM: C = A @ B^T ----------------
// 128x128x32 block tile, 4 warps (2m x 2n), warp tile 64x64, mma.m16n8k8.
#define GBM 128
#define GBN 128
#define GBK 32
#define ASTR 36

__global__ __launch_bounds__(128, 1) void sgemm_tf32(
    const float* __restrict__ A, const float* __restrict__ B,
    float* __restrict__ C, int M, int N, int K)
{
    extern __shared__ float sm[];
    float* Asb[2] = { sm,                  sm + GBM * ASTR };
    float* Bsb[2] = { sm + 2 * GBM * ASTR, sm + 2 * GBM * ASTR + GBN * ASTR };

    int tid = threadIdx.x;
    int bm = blockIdx.y * GBM, bn = blockIdx.x * GBN;
    int lane = tid & 31, wid = tid >> 5;
    int wm = wid & 1, wn = wid >> 1;
    int g = lane >> 2, c4 = lane & 3;

    float acc[4][8][4];
#pragma unroll
    for (int i = 0; i < 4; ++i)
#pragma unroll
        for (int f = 0; f < 8; ++f)
#pragma unroll
            for (int r = 0; r < 4; ++r) acc[i][f][r] = 0.f;

    int lrow = tid >> 3;   // 0..15
    int lq = tid & 7;

    auto load_tiles = [&](int buf, int k0) {
        const float* Ag = A + (size_t)bm * K + k0;
        const float* Bg = B + (size_t)bn * K + k0;
        float* as = Asb[buf];
        float* bs = Bsb[buf];
#pragma unroll
        for (int p = 0; p < 8; ++p) {
            int r = lrow + p * 16;
            cp_async16(as + r * ASTR + lq * 4, Ag + (size_t)r * K + lq * 4);
        }
#pragma unroll
        for (int p = 0; p < 8; ++p) {
            int r = lrow + p * 16;
            cp_async16(bs + r * ASTR + lq * 4, Bg + (size_t)r * K + lq * 4);
        }
    };

    auto compute = [&](int buf) {
        const float* as = Asb[buf];
        const float* bs = Bsb[buf];
#pragma unroll
        for (int ks = 0; ks < 4; ++ks) {
            int kb = ks * 8;
            unsigned af[4][4];
            unsigned bf[8][2];
#pragma unroll
            for (int i = 0; i < 4; ++i) {
                int rb = wm * 64 + i * 16 + g;
                af[i][0] = __float_as_uint(as[(rb)     * ASTR + kb + c4]);
                af[i][1] = __float_as_uint(as[(rb + 8) * ASTR + kb + c4]);
                af[i][2] = __float_as_uint(as[(rb)     * ASTR + kb + c4 + 4]);
                af[i][3] = __float_as_uint(as[(rb + 8) * ASTR + kb + c4 + 4]);
            }
#pragma unroll
            for (int f = 0; f < 8; ++f) {
                int nb = wn * 64 + f * 8 + g;
                bf[f][0] = __float_as_uint(bs[nb * ASTR + kb + c4]);
                bf[f][1] = __float_as_uint(bs[nb * ASTR + kb + c4 + 4]);
            }
#pragma unroll
            for (int i = 0; i < 4; ++i)
#pragma unroll
                for (int f = 0; f < 8; ++f) {
                    asm volatile(
                        "mma.sync.aligned.m16n8k8.row.col.f32.tf32.tf32.f32 "
                        "{%0,%1,%2,%3}, {%4,%5,%6,%7}, {%8,%9}, {%0,%1,%2,%3};"
                        : "+f"(acc[i][f][0]), "+f"(acc[i][f][1]),
                          "+f"(acc[i][f][2]), "+f"(acc[i][f][3])
                        : "r"(af[i][0]), "r"(af[i][1]), "r"(af[i][2]), "r"(af[i][3]),
                          "r"(bf[f][0]), "r"(bf[f][1]));
                }
        }
    };

    int NK = K / GBK;
    load_tiles(0, 0);
    asm volatile("cp.async.commit_group;\n");
    asm volatile("cp.async.wait_group 0;\n");
    __syncthreads();

    for (int it = 0; it < NK; ++it) {
        int cur = it & 1;
        if (it + 1 < NK) {
            load_tiles(cur ^ 1, (it + 1) * GBK);
            asm volatile("cp.async.commit_group;\n");
        }
        compute(cur);
        if (it + 1 < NK) asm volatile("cp.async.wait_group 0;\n");
        __syncthreads();
    }

#pragma unroll
    for (int i = 0; i < 4; ++i) {
        int r0 = bm + wm * 64 + i * 16 + g;
#pragma unroll
        for (int f = 0; f < 8; ++f) {
            int col = bn + wn * 64 + f * 8 + 2 * c4;
            *(float2*)(C + (size_t)r0 * N + col) = make_float2(acc[i][f][0], acc[i][f][1]);
            *(float2*)(C + (size_t)(r0 + 8) * N + col) = make_float2(acc[i][f][2], acc[i][f][3]);
        }
    }
}

// ------------------------- layernorm + leaky_relu ---------------------------
// dst: output buffer (may equal Z); xres: optional residual accumulate target.
__global__ __launch_bounds__(128) void ln_leaky_kernel(
    const float* __restrict__ Z, const float* __restrict__ bias,
    const float* __restrict__ g, const float* __restrict__ beta,
    float* __restrict__ dst, float* __restrict__ xres, int round_out)
{
    __shared__ float sh[8];
    int t = blockIdx.x;
    int tid = threadIdx.x;
    const float* row = Z + (size_t)t * D_DIM;

    float v[4];
    float s = 0.f;
#pragma unroll
    for (int q = 0; q < 4; ++q) {
        int idx = tid + q * 128;
        v[q] = row[idx] + bias[idx];
        s += v[q];
    }
#pragma unroll
    for (int off = 16; off > 0; off >>= 1) s += __shfl_xor_sync(0xffffffffu, s, off);
    if ((tid & 31) == 0) sh[tid >> 5] = s;
    __syncthreads();
    float mean = (sh[0] + sh[1] + sh[2] + sh[3]) * (1.f / D_DIM);

    float vs = 0.f;
#pragma unroll
    for (int q = 0; q < 4; ++q) { float d = v[q] - mean; vs += d * d; }
#pragma unroll
    for (int off = 16; off > 0; off >>= 1) vs += __shfl_xor_sync(0xffffffffu, vs, off);
    if ((tid & 31) == 0) sh[4 + (tid >> 5)] = vs;
    __syncthreads();
    float var = (sh[4] + sh[5] + sh[6] + sh[7]) * (1.f / D_DIM);
    float rstd = rsqrtf(var + 1e-5f);

#pragma unroll
    for (int q = 0; q < 4; ++q) {
        int idx = tid + q * 128;
        float y = (v[q] - mean) * rstd * g[idx] + beta[idx];
        y = (y > 0.f) ? y : 0.01f * y;
        if (dst)  dst[(size_t)t * D_DIM + idx] = round_out ? tf32r(y) : y;
        if (xres) xres[(size_t)t * D_DIM + idx] += y;
    }
}

// ------------------------- launch ------------------------------------------
extern "C" void kernel_launch(void* const* d_in, const int* in_sizes, int n_in,
                              void* d_out, int out_size)
{
    const float* x     = (const float*)d_in[0];
    const float* state = (const float*)d_in[1];
    const unsigned int* start = (const unsigned int*)d_in[2];
    const float* Wtr   = (const float*)d_in[3];
    const float* Wc    = (const float*)d_in[4];
    const float* a     = (const float*)d_in[5];
    const float* b     = (const float*)d_in[6];
    const float* W0    = (const float*)d_in[7];
    const float* b0    = (const float*)d_in[8];
    const float* g0    = (const float*)d_in[9];
    const float* be0   = (const float*)d_in[10];
    const float* W1    = (const float*)d_in[11];
    const float* b1    = (const float*)d_in[12];
    const float* g1    = (const float*)d_in[13];
    const float* be1   = (const float*)d_in[14];
    float* out = (float*)d_out;

    float *pX, *pAtr, *pAct, *pInv, *pScaled, *pH, *pZ, *pW0t, *pW1t;
    cudaGetSymbolAddress((void**)&pX, g_X);
    cudaGetSymbolAddress((void**)&pAtr, g_atr);
    cudaGetSymbolAddress((void**)&pAct, g_act);
    cudaGetSymbolAddress((void**)&pInv, g_inv);
    cudaGetSymbolAddress((void**)&pScaled, g_scaled);
    cudaGetSymbolAddress((void**)&pH, g_h);
    cudaGetSymbolAddress((void**)&pZ, g_z);
    cudaGetSymbolAddress((void**)&pW0t, g_W0t);
    cudaGetSymbolAddress((void**)&pW1t, g_W1t);

    const int SMEM_GEMM = 2 * (GBM + GBN) * ASTR * (int)sizeof(float);  // 73728
    cudaFuncSetAttribute(sgemm_tf32, cudaFuncAttributeMaxDynamicSharedMemorySize, SMEM_GEMM);

    const int ND = T_LEN * D_DIM;
    copy_kernel<<<512, 256>>>(pX, x, ND);
    tf32_round_kernel<<<1024, 256>>>(pW0t, W0, L_NUM * D_DIM * F_DIM);
    tf32_round_kernel<<<256, 256>>>(pW1t, W1, L_NUM * D_DIM * D_DIM);

    dim3 ggrid(D_DIM / GBN, T_LEN / GBM);   // (4, 32)
    dim3 sgrid(TR_DIM, NCH);                // (64, 64)

    for (int l = 0; l < L_NUM; ++l) {
        proj_gemm_kernel<<<T_LEN / PBM, 256>>>(
            pX, Wtr + (size_t)l * TR_DIM * D_DIM,
            Wc + (size_t)l * CC_DIM * D_DIM, pAtr, pAct, pInv);
        scan_chunkA_kernel<<<sgrid, 32>>>(
            pAtr, pAct, pInv, start,
            a + (size_t)l * TR_DIM, b + (size_t)l * CC_DIM);
        scan_combine_kernel<<<NCHAN / 256, 256>>>(
            state + (size_t)l * TR_DIM * CC_DIM);
        scan_chunkC_kernel<<<sgrid, 32>>>(
            pAtr, pAct, pInv, start,
            a + (size_t)l * TR_DIM, b + (size_t)l * CC_DIM, pScaled);
        sgemm_tf32<<<ggrid, 128, SMEM_GEMM>>>(
            pScaled, pW0t + (size_t)l * D_DIM * F_DIM, pH, T_LEN, D_DIM, F_DIM);
        ln_leaky_kernel<<<T_LEN, 128>>>(pH, b0 + (size_t)l * D_DIM,
                                        g0 + (size_t)l * D_DIM,
                                        be0 + (size_t)l * D_DIM, pH, nullptr, 1);
        sgemm_tf32<<<ggrid, 128, SMEM_GEMM>>>(
            pH, pW1t + (size_t)l * D_DIM * D_DIM, pZ, T_LEN, D_DIM, D_DIM);
        if (l < L_NUM - 1) {
            // write residual into X only (z not needed separately)
            ln_leaky_kernel<<<T_LEN, 128>>>(pZ, b1 + (size_t)l * D_DIM,
                                            g1 + (size_t)l * D_DIM,
                                            be1 + (size_t)l * D_DIM,
                                            nullptr, pX, 0);
        } else {
            // final layer: write straight to output
            ln_leaky_kernel<<<T_LEN, 128>>>(pZ, b1 + (size_t)l * D_DIM,
                                            g1 + (size_t)l * D_DIM,
                                            be1 + (size_t)l * D_DIM,
                                            out, nullptr, 0);
        }
    }
}

// round 6
// speedup vs baseline: 11.1203x; 1.6020x over previous
#include <cuda_runtime.h>
#include <cuda_bf16.h>
#include <cuda_fp16.h>
#include <math.h>

#define T_LEN 4096
#define D_DIM 512
#define TR_DIM 64
#define CC_DIM 64
#define F_DIM 8192   // 2*TR*CC
#define L_NUM 3
#define NCH 64       // scan chunks
#define CHUNK 64     // timesteps per chunk
#define NCHAN (TR_DIM * CC_DIM)

#define FSCALE 64.0f     // feature pre-scale (A of GEMM0)
#define W0SCALE 32.0f    // W0 pre-scale (B of GEMM0)
#define ISCALE0 (1.0f / (FSCALE * W0SCALE))

// ------------------------- scratch (device globals; no alloc) ---------------
__device__ float  g_X[(size_t)T_LEN * D_DIM];
__device__ float  g_atr[(size_t)T_LEN * TR_DIM];
__device__ float  g_act[(size_t)T_LEN * CC_DIM];
__device__ float  g_inv[T_LEN];
__device__ __half g_scaledh[(size_t)T_LEN * F_DIM];
__device__ float  g_h[(size_t)T_LEN * D_DIM];
__device__ __half g_hh[(size_t)T_LEN * D_DIM];
__device__ float  g_z[(size_t)T_LEN * D_DIM];
__device__ __half g_W0h[(size_t)L_NUM * D_DIM * F_DIM];
__device__ __half g_W1h[(size_t)L_NUM * D_DIM * D_DIM];
__device__ float  g_cAr[(size_t)NCH * NCHAN];
__device__ float  g_cAi[(size_t)NCH * NCHAN];
__device__ float  g_cBr[(size_t)NCH * NCHAN];
__device__ float  g_cBi[(size_t)NCH * NCHAN];
__device__ float  g_sinr[(size_t)NCH * NCHAN];
__device__ float  g_sini[(size_t)NCH * NCHAN];

__device__ __forceinline__ void cp_async16(void* smem_dst, const void* gsrc) {
    unsigned saddr = (unsigned)__cvta_generic_to_shared(smem_dst);
    asm volatile("cp.async.cg.shared.global [%0], [%1], 16;\n" :: "r"(saddr), "l"(gsrc));
}

// ------------------------- small utility kernels ----------------------------
__global__ void copy_kernel(float* __restrict__ dst, const float* __restrict__ src, int n) {
    int i = blockIdx.x * blockDim.x + threadIdx.x;
    int stride = gridDim.x * blockDim.x;
    for (; i < n; i += stride) dst[i] = src[i];
}

__global__ void half_convert_kernel(__half* __restrict__ dst, const float* __restrict__ src,
                                    int n, float scale) {
    int i = blockIdx.x * blockDim.x + threadIdx.x;
    int stride = gridDim.x * blockDim.x;
    for (; i < n; i += stride) dst[i] = __float2half_rn(src[i] * scale);
}

// ------------------------- fused projection GEMM ----------------------------
#define PBM 32
#define PBK 32
__global__ __launch_bounds__(256) void proj_gemm_kernel(
    const float* __restrict__ X, const float* __restrict__ Wtr,
    const float* __restrict__ Wc, float* __restrict__ atr,
    float* __restrict__ act, float* __restrict__ inv)
{
    __shared__ float Xs[PBK][PBM + 4];
    __shared__ float Ws[PBK][128 + 4];
    __shared__ float red[PBM][2];

    int tid = threadIdx.x;
    int bm = blockIdx.x * PBM;
    int tx = tid & 31;
    int ty = tid >> 5;

    if (tid < 64) red[tid >> 1][tid & 1] = 0.f;

    float acc[4][4];
#pragma unroll
    for (int i = 0; i < 4; ++i)
#pragma unroll
        for (int j = 0; j < 4; ++j) acc[i][j] = 0.f;

    int lr = tid >> 3;
    int c4 = tid & 7;

    for (int k0 = 0; k0 < D_DIM; k0 += PBK) {
        {
            float4 v = *(const float4*)(X + (size_t)(bm + lr) * D_DIM + k0 + c4 * 4);
            Xs[c4 * 4 + 0][lr] = v.x;
            Xs[c4 * 4 + 1][lr] = v.y;
            Xs[c4 * 4 + 2][lr] = v.z;
            Xs[c4 * 4 + 3][lr] = v.w;
        }
#pragma unroll
        for (int p = 0; p < 4; ++p) {
            int row = lr + p * 32;
            const float* Wrow = (row < 64) ? (Wtr + (size_t)row * D_DIM)
                                           : (Wc + (size_t)(row - 64) * D_DIM);
            float4 v = *(const float4*)(Wrow + k0 + c4 * 4);
            Ws[c4 * 4 + 0][row] = v.x;
            Ws[c4 * 4 + 1][row] = v.y;
            Ws[c4 * 4 + 2][row] = v.z;
            Ws[c4 * 4 + 3][row] = v.w;
        }
        __syncthreads();

#pragma unroll
        for (int kk = 0; kk < PBK; ++kk) {
            float xv[4], wv[4];
#pragma unroll
            for (int i = 0; i < 4; ++i) xv[i] = Xs[kk][ty * 4 + i];
#pragma unroll
            for (int j = 0; j < 4; ++j) wv[j] = Ws[kk][tx * 4 + j];
#pragma unroll
            for (int i = 0; i < 4; ++i)
#pragma unroll
                for (int j = 0; j < 4; ++j) acc[i][j] += xv[i] * wv[j];
        }
        __syncthreads();
    }

    int half_sel = (tx >= 16);
#pragma unroll
    for (int i = 0; i < 4; ++i) {
        int tok = ty * 4 + i;
        float psum = 0.f;
#pragma unroll
        for (int j = 0; j < 4; ++j) {
            float av = fabsf(acc[i][j]);
            psum += av;
            int o = tx * 4 + j;
            if (o < 64) atr[(size_t)(bm + tok) * TR_DIM + o] = av;
            else        act[(size_t)(bm + tok) * CC_DIM + o - 64] = av;
        }
        atomicAdd(&red[tok][half_sel], psum);
    }
    __syncthreads();
    if (tid < 32)
        inv[bm + tid] = 1.f / (1e-8f + red[tid][0] * red[tid][1]);
}

// ------------------------- scan pass A: chunk (A,B) --------------------------
__global__ __launch_bounds__(32) void scan_chunkA_kernel(
    const float* __restrict__ atr, const float* __restrict__ act,
    const float* __restrict__ inv, const unsigned int* __restrict__ start,
    const float* __restrict__ a, const float* __restrict__ b)
{
    __shared__ float ativ[CHUNK];
    __shared__ unsigned sfl[CHUNK];
    int i = blockIdx.x;
    int cidx = blockIdx.y;
    int tid = threadIdx.x;
    int t0 = cidx * CHUNK;

#pragma unroll
    for (int q = 0; q < 2; ++q) {
        int idx = tid + q * 32;
        int t = t0 + idx;
        ativ[idx] = atr[(size_t)t * TR_DIM + i] * inv[t];
        sfl[idx] = start[t];
    }
    __syncwarp();

    float mag = expf(-fabsf(a[i]));
    int j0 = tid, j1 = tid + 32;
    float b0 = b[j0], b1 = b[j1];
    float dr0 = mag * cosf(b0), di0 = mag * sinf(b0);
    float dr1 = mag * cosf(b1), di1 = mag * sinf(b1);

    float pr0 = dr0, pi0 = di0, pr1 = dr1, pi1 = di1;
#pragma unroll
    for (int q = 0; q < 6; ++q) {
        float n0r = pr0 * pr0 - pi0 * pi0, n0i = 2.f * pr0 * pi0;
        float n1r = pr1 * pr1 - pi1 * pi1, n1i = 2.f * pr1 * pi1;
        pr0 = n0r; pi0 = n0i; pr1 = n1r; pi1 = n1i;
    }

    float sr0 = 0.f, si0 = 0.f, sr1 = 0.f, si1 = 0.f;
    unsigned any = 0;

#pragma unroll 4
    for (int tt = 0; tt < CHUNK; ++tt) {
        float av = ativ[tt];
        unsigned st = sfl[tt];
        any |= st;
        const float* acp = act + (size_t)(t0 + tt) * CC_DIM;
        float p0 = av * acp[j0];
        float p1 = av * acp[j1];
        if (st) { sr0 = 0.f; si0 = 0.f; sr1 = 0.f; si1 = 0.f; }
        float n0r = sr0 * dr0 - si0 * di0 + p0;
        float n0i = sr0 * di0 + si0 * dr0;
        float n1r = sr1 * dr1 - si1 * di1 + p1;
        float n1i = sr1 * di1 + si1 * dr1;
        sr0 = n0r; si0 = n0i; sr1 = n1r; si1 = n1i;
    }

    size_t o0 = (size_t)cidx * NCHAN + i * CC_DIM + j0;
    size_t o1 = o0 + 32;
    float am = any ? 0.f : 1.f;
    g_cAr[o0] = am * pr0; g_cAi[o0] = am * pi0;
    g_cAr[o1] = am * pr1; g_cAi[o1] = am * pi1;
    g_cBr[o0] = sr0; g_cBi[o0] = si0;
    g_cBr[o1] = sr1; g_cBi[o1] = si1;
}

// ------------------------- scan pass B: combine chunks -----------------------
__global__ __launch_bounds__(256) void scan_combine_kernel(const float* __restrict__ st0)
{
    int ch = blockIdx.x * blockDim.x + threadIdx.x;
    if (ch >= NCHAN) return;
    float sr = st0[ch];
    float si = 0.f;
    for (int c = 0; c < NCH; ++c) {
        size_t o = (size_t)c * NCHAN + ch;
        g_sinr[o] = sr; g_sini[o] = si;
        float ar = g_cAr[o], ai = g_cAi[o];
        float nsr = sr * ar - si * ai + g_cBr[o];
        float nsi = sr * ai + si * ar + g_cBi[o];
        sr = nsr; si = nsi;
    }
}

// ------------------------- scan pass C: rescan + features --------------------
__device__ __forceinline__ float featf(float sr, float si) {
    float r2 = fmaxf(sr * sr + si * si, 1e-34f);
    float rr = rsqrtf(r2);
    float r = r2 * rr;
    float flog = __logf(1.f + r) * rr;
    float fpoly = 1.f - r * (0.5f - r * (1.f / 3.f));
    return (r < 0.03f) ? fpoly : flog;
}

__global__ __launch_bounds__(32) void scan_chunkC_kernel(
    const float* __restrict__ atr, const float* __restrict__ act,
    const float* __restrict__ inv, const unsigned int* __restrict__ start,
    const float* __restrict__ a, const float* __restrict__ b,
    __half* __restrict__ scaled)
{
    __shared__ float ativ[CHUNK];
    __shared__ unsigned sfl[CHUNK];
    int i = blockIdx.x;
    int cidx = blockIdx.y;
    int tid = threadIdx.x;
    int t0 = cidx * CHUNK;

#pragma unroll
    for (int q = 0; q < 2; ++q) {
        int idx = tid + q * 32;
        int t = t0 + idx;
        ativ[idx] = atr[(size_t)t * TR_DIM + i] * inv[t];
        sfl[idx] = start[t];
    }
    __syncwarp();

    float mag = expf(-fabsf(a[i]));
    int j0 = tid, j1 = tid + 32;
    float b0 = b[j0], b1 = b[j1];
    float dr0 = mag * cosf(b0), di0 = mag * sinf(b0);
    float dr1 = mag * cosf(b1), di1 = mag * sinf(b1);

    int ch0 = i * CC_DIM + j0;
    size_t o0 = (size_t)cidx * NCHAN + ch0;
    float sr0 = g_sinr[o0], si0 = g_sini[o0];
    float sr1 = g_sinr[o0 + 32], si1 = g_sini[o0 + 32];

#pragma unroll 2
    for (int tt = 0; tt < CHUNK; ++tt) {
        int t = t0 + tt;
        float av = ativ[tt];
        unsigned st = sfl[tt];
        const float* acp = act + (size_t)t * CC_DIM;
        float p0 = av * acp[j0];
        float p1 = av * acp[j1];
        if (st) { sr0 = 0.f; si0 = 0.f; sr1 = 0.f; si1 = 0.f; }
        float n0r = sr0 * dr0 - si0 * di0 + p0;
        float n0i = sr0 * di0 + si0 * dr0;
        float n1r = sr1 * dr1 - si1 * di1 + p1;
        float n1i = sr1 * di1 + si1 * dr1;
        sr0 = n0r; si0 = n0i; sr1 = n1r; si1 = n1i;

        float f0 = featf(sr0, si0) * FSCALE;
        float f1 = featf(sr1, si1) * FSCALE;
        __half* row = scaled + (size_t)t * F_DIM;
        row[ch0]              = __float2half_rn(f0 * si0);
        row[ch0 + 32]         = __float2half_rn(f1 * si1);
        row[ch0 + NCHAN]      = __float2half_rn(f0 * sr0);
        row[ch0 + 32 + NCHAN] = __float2half_rn(f1 * sr1);
    }
}

// ------------------------- FP16 tensor-core GEMM: C = A @ B^T ----------------
// A: MxK row-major __half, B: NxK row-major __half, C fp32.
// 128x128x64 block tile, 4 warps (2m x 2n), warp tile 64x64, mma.m16n8k16.
#define GBM 128
#define GBN 128
#define GBK 64
#define HSTR 72   // halves per smem row (64 + 8 pad) -> conflict-free frags

__global__ __launch_bounds__(128, 1) void gemm_f16(
    const __half* __restrict__ A, const __half* __restrict__ B,
    float* __restrict__ C, int M, int N, int K)
{
    extern __shared__ __half smh[];
    __half* Asb[2] = { smh,                  smh + GBM * HSTR };
    __half* Bsb[2] = { smh + 2 * GBM * HSTR, smh + 2 * GBM * HSTR + GBN * HSTR };

    int tid = threadIdx.x;
    int bm = blockIdx.y * GBM, bn = blockIdx.x * GBN;
    int lane = tid & 31, wid = tid >> 5;
    int wm = wid & 1, wn = wid >> 1;
    int g = lane >> 2, c4 = lane & 3;

    float acc[4][8][4];
#pragma unroll
    for (int i = 0; i < 4; ++i)
#pragma unroll
        for (int f = 0; f < 8; ++f)
#pragma unroll
            for (int r = 0; r < 4; ++r) acc[i][f][r] = 0.f;

    int lrow = tid >> 3;   // 0..15
    int lq = tid & 7;      // 16B chunk (8 halves)

    auto load_tiles = [&](int buf, int k0) {
        const __half* Ag = A + (size_t)bm * K + k0;
        const __half* Bg = B + (size_t)bn * K + k0;
        __half* as = Asb[buf];
        __half* bs = Bsb[buf];
#pragma unroll
        for (int p = 0; p < 8; ++p) {
            int r = lrow + p * 16;
            cp_async16(as + r * HSTR + lq * 8, Ag + (size_t)r * K + lq * 8);
        }
#pragma unroll
        for (int p = 0; p < 8; ++p) {
            int r = lrow + p * 16;
            cp_async16(bs + r * HSTR + lq * 8, Bg + (size_t)r * K + lq * 8);
        }
    };

    auto compute = [&](int buf) {
        const __half* as = Asb[buf];
        const __half* bs = Bsb[buf];
#pragma unroll
        for (int ks = 0; ks < 4; ++ks) {
            int kb = ks * 16;
            unsigned af[4][4];
            unsigned bf[8][2];
#pragma unroll
            for (int i = 0; i < 4; ++i) {
                int rb = wm * 64 + i * 16 + g;
                af[i][0] = *(const unsigned*)&as[(rb)     * HSTR + kb + 2 * c4];
                af[i][1] = *(const unsigned*)&as[(rb + 8) * HSTR + kb + 2 * c4];
                af[i][2] = *(const unsigned*)&as[(rb)     * HSTR + kb + 8 + 2 * c4];
                af[i][3] = *(const unsigned*)&as[(rb + 8) * HSTR + kb + 8 + 2 * c4];
            }
#pragma unroll
            for (int f = 0; f < 8; ++f) {
                int nb = wn * 64 + f * 8 + g;
                bf[f][0] = *(const unsigned*)&bs[nb * HSTR + kb + 2 * c4];
                bf[f][1] = *(const unsigned*)&bs[nb * HSTR + kb + 8 + 2 * c4];
            }
#pragma unroll
            for (int i = 0; i < 4; ++i)
#pragma unroll
                for (int f = 0; f < 8; ++f) {
                    asm volatile(
                        "mma.sync.aligned.m16n8k16.row.col.f32.f16.f16.f32 "
                        "{%0,%1,%2,%3}, {%4,%5,%6,%7}, {%8,%9}, {%0,%1,%2,%3};"
                        : "+f"(acc[i][f][0]), "+f"(acc[i][f][1]),
                          "+f"(acc[i][f][2]), "+f"(acc[i][f][3])
                        : "r"(af[i][0]), "r"(af[i][1]), "r"(af[i][2]), "r"(af[i][3]),
                          "r"(bf[f][0]), "r"(bf[f][1]));
                }
        }
    };

    int NK = K / GBK;
    load_tiles(0, 0);
    asm volatile("cp.async.commit_group;\n");
    asm volatile("cp.async.wait_group 0;\n");
    __syncthreads();

    for (int it = 0; it < NK; ++it) {
        int cur = it & 1;
        if (it + 1 < NK) {
            load_tiles(cur ^ 1, (it + 1) * GBK);
            asm volatile("cp.async.commit_group;\n");
        }
        compute(cur);
        if (it + 1 < NK) asm volatile("cp.async.wait_group 0;\n");
        __syncthreads();
    }

#pragma unroll
    for (int i = 0; i < 4; ++i) {
        int r0 = bm + wm * 64 + i * 16 + g;
#pragma unroll
        for (int f = 0; f < 8; ++f) {
            int col = bn + wn * 64 + f * 8 + 2 * c4;
            *(float2*)(C + (size_t)r0 * N + col) = make_float2(acc[i][f][0], acc[i][f][1]);
            *(float2*)(C + (size_t)(r0 + 8) * N + col) = make_float2(acc[i][f][2], acc[i][f][3]);
        }
    }
}

// ------------------------- layernorm + leaky_relu ---------------------------
// iscale: unscale GEMM output before bias (exact; applied pre-normalization).
// dsth: fp16 output for next GEMM; dstf: fp32 output; xres: residual target.
__global__ __launch_bounds__(128) void ln_leaky_kernel(
    const float* __restrict__ Z, const float* __restrict__ bias,
    const float* __restrict__ g, const float* __restrict__ beta,
    float iscale, float* __restrict__ dstf, __half* __restrict__ dsth,
    float* __restrict__ xres)
{
    __shared__ float sh[8];
    int t = blockIdx.x;
    int tid = threadIdx.x;
    const float* row = Z + (size_t)t * D_DIM;

    float v[4];
    float s = 0.f;
#pragma unroll
    for (int q = 0; q < 4; ++q) {
        int idx = tid + q * 128;
        v[q] = row[idx] * iscale + bias[idx];
        s += v[q];
    }
#pragma unroll
    for (int off = 16; off > 0; off >>= 1) s += __shfl_xor_sync(0xffffffffu, s, off);
    if ((tid & 31) == 0) sh[tid >> 5] = s;
    __syncthreads();
    float mean = (sh[0] + sh[1] + sh[2] + sh[3]) * (1.f / D_DIM);

    float vs = 0.f;
#pragma unroll
    for (int q = 0; q < 4; ++q) { float d = v[q] - mean; vs += d * d; }
#pragma unroll
    for (int off = 16; off > 0; off >>= 1) vs += __shfl_xor_sync(0xffffffffu, vs, off);
    if ((tid & 31) == 0) sh[4 + (tid >> 5)] = vs;
    __syncthreads();
    float var = (sh[4] + sh[5] + sh[6] + sh[7]) * (1.f / D_DIM);
    float rstd = rsqrtf(var + 1e-5f);

#pragma unroll
    for (int q = 0; q < 4; ++q) {
        int idx = tid + q * 128;
        float y = (v[q] - mean) * rstd * g[idx] + beta[idx];
        y = (y > 0.f) ? y : 0.01f * y;
        if (dstf) dstf[(size_t)t * D_DIM + idx] = y;
        if (dsth) dsth[(size_t)t * D_DIM + idx] = __float2half_rn(y);
        if (xres) xres[(size_t)t * D_DIM + idx] += y;
    }
}

// ------------------------- launch ------------------------------------------
extern "C" void kernel_launch(void* const* d_in, const int* in_sizes, int n_in,
                              void* d_out, int out_size)
{
    const float* x     = (const float*)d_in[0];
    const float* state = (const float*)d_in[1];
    const unsigned int* start = (const unsigned int*)d_in[2];
    const float* Wtr   = (const float*)d_in[3];
    const float* Wc    = (const float*)d_in[4];
    const float* a     = (const float*)d_in[5];
    const float* b     = (const float*)d_in[6];
    const float* W0    = (const float*)d_in[7];
    const float* b0    = (const float*)d_in[8];
    const float* g0    = (const float*)d_in[9];
    const float* be0   = (const float*)d_in[10];
    const float* W1    = (const float*)d_in[11];
    const float* b1    = (const float*)d_in[12];
    const float* g1    = (const float*)d_in[13];
    const float* be1   = (const float*)d_in[14];
    float* out = (float*)d_out;

    float *pX, *pAtr, *pAct, *pInv, *pH, *pZ;
    __half *pScaledH, *pHH, *pW0h, *pW1h;
    cudaGetSymbolAddress((void**)&pX, g_X);
    cudaGetSymbolAddress((void**)&pAtr, g_atr);
    cudaGetSymbolAddress((void**)&pAct, g_act);
    cudaGetSymbolAddress((void**)&pInv, g_inv);
    cudaGetSymbolAddress((void**)&pScaledH, g_scaledh);
    cudaGetSymbolAddress((void**)&pH, g_h);
    cudaGetSymbolAddress((void**)&pHH, g_hh);
    cudaGetSymbolAddress((void**)&pZ, g_z);
    cudaGetSymbolAddress((void**)&pW0h, g_W0h);
    cudaGetSymbolAddress((void**)&pW1h, g_W1h);

    const int SMEM_GEMM = 2 * (GBM + GBN) * HSTR * (int)sizeof(__half);  // 73728
    cudaFuncSetAttribute(gemm_f16, cudaFuncAttributeMaxDynamicSharedMemorySize, SMEM_GEMM);

    const int ND = T_LEN * D_DIM;
    copy_kernel<<<512, 256>>>(pX, x, ND);
    half_convert_kernel<<<1024, 256>>>(pW0h, W0, L_NUM * D_DIM * F_DIM, W0SCALE);
    half_convert_kernel<<<256, 256>>>(pW1h, W1, L_NUM * D_DIM * D_DIM, 1.0f);

    dim3 ggrid(D_DIM / GBN, T_LEN / GBM);   // (4, 32)
    dim3 sgrid(TR_DIM, NCH);                // (64, 64)

    for (int l = 0; l < L_NUM; ++l) {
        proj_gemm_kernel<<<T_LEN / PBM, 256>>>(
            pX, Wtr + (size_t)l * TR_DIM * D_DIM,
            Wc + (size_t)l * CC_DIM * D_DIM, pAtr, pAct, pInv);
        scan_chunkA_kernel<<<sgrid, 32>>>(
            pAtr, pAct, pInv, start,
            a + (size_t)l * TR_DIM, b + (size_t)l * CC_DIM);
        scan_combine_kernel<<<NCHAN / 256, 256>>>(
            state + (size_t)l * TR_DIM * CC_DIM);
        scan_chunkC_kernel<<<sgrid, 32>>>(
            pAtr, pAct, pInv, start,
            a + (size_t)l * TR_DIM, b + (size_t)l * CC_DIM, pScaledH);
        gemm_f16<<<ggrid, 128, SMEM_GEMM>>>(
            pScaledH, pW0h + (size_t)l * D_DIM * F_DIM, pH, T_LEN, D_DIM, F_DIM);
        ln_leaky_kernel<<<T_LEN, 128>>>(pH, b0 + (size_t)l * D_DIM,
                                        g0 + (size_t)l * D_DIM,
                                        be0 + (size_t)l * D_DIM,
                                        ISCALE0, nullptr, pHH, nullptr);
        gemm_f16<<<ggrid, 128, SMEM_GEMM>>>(
            pHH, pW1h + (size_t)l * D_DIM * D_DIM, pZ, T_LEN, D_DIM, D_DIM);
        if (l < L_NUM - 1) {
            ln_leaky_kernel<<<T_LEN, 128>>>(pZ, b1 + (size_t)l * D_DIM,
                                            g1 + (size_t)l * D_DIM,
                                            be1 + (size_t)l * D_DIM,
                                            1.0f, nullptr, nullptr, pX);
        } else {
            ln_leaky_kernel<<<T_LEN, 128>>>(pZ, b1 + (size_t)l * D_DIM,
                                            g1 + (size_t)l * D_DIM,
                                            be1 + (size_t)l * D_DIM,
                                            1.0f, out, nullptr, nullptr);
        }
    }
}

// round 9
// speedup vs baseline: 12.3139x; 1.1073x over previous
#include <cuda_runtime.h>
#include <cuda_bf16.h>
#include <cuda_fp16.h>
#include <math.h>

#define T_LEN 4096
#define D_DIM 512
#define TR_DIM 64
#define CC_DIM 64
#define F_DIM 8192   // 2*TR*CC
#define L_NUM 3
#define NCH 64       // scan chunks
#define CHUNK 64     // timesteps per chunk
#define NCHAN (TR_DIM * CC_DIM)

#define FSCALE 64.0f     // feature pre-scale (A of GEMM0)
#define W0SCALE 32.0f    // W0 pre-scale (B of GEMM0)
#define ISCALE0 (1.0f / (FSCALE * W0SCALE))

// ------------------------- scratch (device globals; no alloc) ---------------
__device__ float  g_X[(size_t)T_LEN * D_DIM];
__device__ float  g_atr[(size_t)T_LEN * TR_DIM];
__device__ float  g_act[(size_t)T_LEN * CC_DIM];
__device__ float  g_inv[T_LEN];
__device__ __half g_scaledh[(size_t)T_LEN * F_DIM];
__device__ float  g_h[(size_t)T_LEN * D_DIM];
__device__ __half g_hh[(size_t)T_LEN * D_DIM];
__device__ float  g_z[(size_t)T_LEN * D_DIM];
__device__ __half g_W0h[(size_t)L_NUM * D_DIM * F_DIM];
__device__ __half g_W1h[(size_t)L_NUM * D_DIM * D_DIM];
__device__ float  g_cAr[(size_t)NCH * NCHAN];
__device__ float  g_cAi[(size_t)NCH * NCHAN];
__device__ float  g_cBr[(size_t)NCH * NCHAN];
__device__ float  g_cBi[(size_t)NCH * NCHAN];
__device__ float  g_sinr[(size_t)NCH * NCHAN];
__device__ float  g_sini[(size_t)NCH * NCHAN];

__device__ __forceinline__ void cp_async16(void* smem_dst, const void* gsrc) {
    unsigned saddr = (unsigned)__cvta_generic_to_shared(smem_dst);
    asm volatile("cp.async.cg.shared.global [%0], [%1], 16;\n" :: "r"(saddr), "l"(gsrc));
}

__device__ __forceinline__ void ldsm_x4(unsigned& r0, unsigned& r1, unsigned& r2,
                                        unsigned& r3, const __half* p) {
    unsigned addr = (unsigned)__cvta_generic_to_shared(p);
    asm volatile("ldmatrix.sync.aligned.m8n8.x4.shared.b16 {%0,%1,%2,%3}, [%4];"
                 : "=r"(r0), "=r"(r1), "=r"(r2), "=r"(r3) : "r"(addr));
}

// ------------------------- small utility kernels ----------------------------
__global__ void copy_kernel(float* __restrict__ dst, const float* __restrict__ src, int n) {
    int i = blockIdx.x * blockDim.x + threadIdx.x;
    int stride = gridDim.x * blockDim.x;
    for (; i < n; i += stride) dst[i] = src[i];
}

__global__ void half_convert_kernel(__half* __restrict__ dst, const float* __restrict__ src,
                                    int n, float scale) {
    int i = blockIdx.x * blockDim.x + threadIdx.x;
    int stride = gridDim.x * blockDim.x;
    for (; i < n; i += stride) dst[i] = __float2half_rn(src[i] * scale);
}

// ------------------------- fused projection GEMM ----------------------------
// Block: 16 tokens x 128 outputs (64 tr + 64 ct), K=512. Grid = 256 blocks.
#define PBM 16
#define PBK 32
__global__ __launch_bounds__(256) void proj_gemm_kernel(
    const float* __restrict__ X, const float* __restrict__ Wtr,
    const float* __restrict__ Wc, float* __restrict__ atr,
    float* __restrict__ act, float* __restrict__ inv)
{
    __shared__ float Xs[PBK][PBM + 4];
    __shared__ float Ws[PBK][128 + 4];
    __shared__ float red[PBM][2];

    int tid = threadIdx.x;
    int bm = blockIdx.x * PBM;
    int tx = tid & 31;    // output dir: 4 each
    int ty = tid >> 5;    // token dir:  2 each

    if (tid < 32) red[tid >> 1][tid & 1] = 0.f;

    float acc[2][4];
#pragma unroll
    for (int i = 0; i < 2; ++i)
#pragma unroll
        for (int j = 0; j < 4; ++j) acc[i][j] = 0.f;

    int lr = tid >> 3;   // 0..31
    int c4 = tid & 7;    // 0..7

    for (int k0 = 0; k0 < D_DIM; k0 += PBK) {
        // X tile 16x32: 128 float4, threads 0..127
        if (tid < 128) {
            int row = tid >> 3, cc = tid & 7;
            float4 v = *(const float4*)(X + (size_t)(bm + row) * D_DIM + k0 + cc * 4);
            Xs[cc * 4 + 0][row] = v.x;
            Xs[cc * 4 + 1][row] = v.y;
            Xs[cc * 4 + 2][row] = v.z;
            Xs[cc * 4 + 3][row] = v.w;
        }
        // W tile 128x32: 1024 float4, 4 per thread
#pragma unroll
        for (int p = 0; p < 4; ++p) {
            int row = lr + p * 32;
            const float* Wrow = (row < 64) ? (Wtr + (size_t)row * D_DIM)
                                           : (Wc + (size_t)(row - 64) * D_DIM);
            float4 v = *(const float4*)(Wrow + k0 + c4 * 4);
            Ws[c4 * 4 + 0][row] = v.x;
            Ws[c4 * 4 + 1][row] = v.y;
            Ws[c4 * 4 + 2][row] = v.z;
            Ws[c4 * 4 + 3][row] = v.w;
        }
        __syncthreads();

#pragma unroll
        for (int kk = 0; kk < PBK; ++kk) {
            float xv[2], wv[4];
#pragma unroll
            for (int i = 0; i < 2; ++i) xv[i] = Xs[kk][ty * 2 + i];
#pragma unroll
            for (int j = 0; j < 4; ++j) wv[j] = Ws[kk][tx * 4 + j];
#pragma unroll
            for (int i = 0; i < 2; ++i)
#pragma unroll
                for (int j = 0; j < 4; ++j) acc[i][j] += xv[i] * wv[j];
        }
        __syncthreads();
    }

    int half_sel = (tx >= 16);
#pragma unroll
    for (int i = 0; i < 2; ++i) {
        int tok = ty * 2 + i;
        float psum = 0.f;
#pragma unroll
        for (int j = 0; j < 4; ++j) {
            float av = fabsf(acc[i][j]);
            psum += av;
            int o = tx * 4 + j;
            if (o < 64) atr[(size_t)(bm + tok) * TR_DIM + o] = av;
            else        act[(size_t)(bm + tok) * CC_DIM + o - 64] = av;
        }
        atomicAdd(&red[tok][half_sel], psum);
    }
    __syncthreads();
    if (tid < 16)
        inv[bm + tid] = 1.f / (1e-8f + red[tid][0] * red[tid][1]);
}

// ------------------------- scan pass A: chunk (A,B) --------------------------
__global__ __launch_bounds__(32) void scan_chunkA_kernel(
    const float* __restrict__ atr, const float* __restrict__ act,
    const float* __restrict__ inv, const unsigned int* __restrict__ start,
    const float* __restrict__ a, const float* __restrict__ b)
{
    __shared__ float ativ[CHUNK];
    __shared__ unsigned sfl[CHUNK];
    int i = blockIdx.x;
    int cidx = blockIdx.y;
    int tid = threadIdx.x;
    int t0 = cidx * CHUNK;

#pragma unroll
    for (int q = 0; q < 2; ++q) {
        int idx = tid + q * 32;
        int t = t0 + idx;
        ativ[idx] = atr[(size_t)t * TR_DIM + i] * inv[t];
        sfl[idx] = start[t];
    }
    __syncwarp();

    float mag = expf(-fabsf(a[i]));
    int j0 = tid, j1 = tid + 32;
    float b0 = b[j0], b1 = b[j1];
    float dr0 = mag * cosf(b0), di0 = mag * sinf(b0);
    float dr1 = mag * cosf(b1), di1 = mag * sinf(b1);

    float pr0 = dr0, pi0 = di0, pr1 = dr1, pi1 = di1;
#pragma unroll
    for (int q = 0; q < 6; ++q) {
        float n0r = pr0 * pr0 - pi0 * pi0, n0i = 2.f * pr0 * pi0;
        float n1r = pr1 * pr1 - pi1 * pi1, n1i = 2.f * pr1 * pi1;
        pr0 = n0r; pi0 = n0i; pr1 = n1r; pi1 = n1i;
    }

    float sr0 = 0.f, si0 = 0.f, sr1 = 0.f, si1 = 0.f;
    unsigned any = 0;

#pragma unroll 4
    for (int tt = 0; tt < CHUNK; ++tt) {
        float av = ativ[tt];
        unsigned st = sfl[tt];
        any |= st;
        const float* acp = act + (size_t)(t0 + tt) * CC_DIM;
        float p0 = av * acp[j0];
        float p1 = av * acp[j1];
        if (st) { sr0 = 0.f; si0 = 0.f; sr1 = 0.f; si1 = 0.f; }
        float n0r = sr0 * dr0 - si0 * di0 + p0;
        float n0i = sr0 * di0 + si0 * dr0;
        float n1r = sr1 * dr1 - si1 * di1 + p1;
        float n1i = sr1 * di1 + si1 * dr1;
        sr0 = n0r; si0 = n0i; sr1 = n1r; si1 = n1i;
    }

    size_t o0 = (size_t)cidx * NCHAN + i * CC_DIM + j0;
    size_t o1 = o0 + 32;
    float am = any ? 0.f : 1.f;
    g_cAr[o0] = am * pr0; g_cAi[o0] = am * pi0;
    g_cAr[o1] = am * pr1; g_cAi[o1] = am * pi1;
    g_cBr[o0] = sr0; g_cBi[o0] = si0;
    g_cBr[o1] = sr1; g_cBi[o1] = si1;
}

// ------------------------- scan pass B: combine chunks -----------------------
__global__ __launch_bounds__(256) void scan_combine_kernel(const float* __restrict__ st0)
{
    int ch = blockIdx.x * blockDim.x + threadIdx.x;
    if (ch >= NCHAN) return;
    float sr = st0[ch];
    float si = 0.f;
    for (int c = 0; c < NCH; ++c) {
        size_t o = (size_t)c * NCHAN + ch;
        g_sinr[o] = sr; g_sini[o] = si;
        float ar = g_cAr[o], ai = g_cAi[o];
        float nsr = sr * ar - si * ai + g_cBr[o];
        float nsi = sr * ai + si * ar + g_cBi[o];
        sr = nsr; si = nsi;
    }
}

// ------------------------- scan pass C: rescan + features --------------------
__device__ __forceinline__ float featf(float sr, float si) {
    float r2 = fmaxf(sr * sr + si * si, 1e-34f);
    float rr = rsqrtf(r2);
    float r = r2 * rr;
    float flog = __logf(1.f + r) * rr;
    float fpoly = 1.f - r * (0.5f - r * (1.f / 3.f));
    return (r < 0.03f) ? fpoly : flog;
}

__global__ __launch_bounds__(32) void scan_chunkC_kernel(
    const float* __restrict__ atr, const float* __restrict__ act,
    const float* __restrict__ inv, const unsigned int* __restrict__ start,
    const float* __restrict__ a, const float* __restrict__ b,
    __half* __restrict__ scaled)
{
    __shared__ float ativ[CHUNK];
    __shared__ unsigned sfl[CHUNK];
    int i = blockIdx.x;
    int cidx = blockIdx.y;
    int tid = threadIdx.x;
    int t0 = cidx * CHUNK;

#pragma unroll
    for (int q = 0; q < 2; ++q) {
        int idx = tid + q * 32;
        int t = t0 + idx;
        ativ[idx] = atr[(size_t)t * TR_DIM + i] * inv[t];
        sfl[idx] = start[t];
    }
    __syncwarp();

    float mag = expf(-fabsf(a[i]));
    int j0 = tid, j1 = tid + 32;
    float b0 = b[j0], b1 = b[j1];
    float dr0 = mag * cosf(b0), di0 = mag * sinf(b0);
    float dr1 = mag * cosf(b1), di1 = mag * sinf(b1);

    int ch0 = i * CC_DIM + j0;
    size_t o0 = (size_t)cidx * NCHAN + ch0;
    float sr0 = g_sinr[o0], si0 = g_sini[o0];
    float sr1 = g_sinr[o0 + 32], si1 = g_sini[o0 + 32];

#pragma unroll 2
    for (int tt = 0; tt < CHUNK; ++tt) {
        int t = t0 + tt;
        float av = ativ[tt];
        unsigned st = sfl[tt];
        const float* acp = act + (size_t)t * CC_DIM;
        float p0 = av * acp[j0];
        float p1 = av * acp[j1];
        if (st) { sr0 = 0.f; si0 = 0.f; sr1 = 0.f; si1 = 0.f; }
        float n0r = sr0 * dr0 - si0 * di0 + p0;
        float n0i = sr0 * di0 + si0 * dr0;
        float n1r = sr1 * dr1 - si1 * di1 + p1;
        float n1i = sr1 * di1 + si1 * dr1;
        sr0 = n0r; si0 = n0i; sr1 = n1r; si1 = n1i;

        float f0 = featf(sr0, si0) * FSCALE;
        float f1 = featf(sr1, si1) * FSCALE;
        __half* row = scaled + (size_t)t * F_DIM;
        row[ch0]              = __float2half_rn(f0 * si0);
        row[ch0 + 32]         = __float2half_rn(f1 * si1);
        row[ch0 + NCHAN]      = __float2half_rn(f0 * sr0);
        row[ch0 + 32 + NCHAN] = __float2half_rn(f1 * sr1);
    }
}

// ------------------------- FP16 tensor-core GEMM: C = A @ B^T ----------------
// A: MxK row-major __half, B: NxK row-major __half, C fp32.
// 128x128x64 CTA tile, 8 warps (2m x 4n), warp tile 64x32, mma.m16n8k16.
// 4-stage cp.async ring, ldmatrix fragment loads.
#define GBM 128
#define GBN 128
#define GBK 64
#define STAGES 4
#define HSTR 72   // halves per smem row (64 + 8 pad) -> conflict-free ldmatrix

__global__ __launch_bounds__(256, 1) void gemm_f16(
    const __half* __restrict__ A, const __half* __restrict__ B,
    float* __restrict__ C, int M, int N, int K)
{
    extern __shared__ __half smh[];
    // stage s: A at smh + s*(GBM+GBN)*HSTR, B at +GBM*HSTR
    const int STAGE_SZ = (GBM + GBN) * HSTR;

    int tid = threadIdx.x;
    int bm = blockIdx.y * GBM, bn = blockIdx.x * GBN;
    int lane = tid & 31, wid = tid >> 5;
    int wm = wid & 1, wn = wid >> 1;           // 2 x 4 warp grid
    int g = lane >> 2, c4 = lane & 3;
    int lm8 = lane & 7;
    int lsel8 = ((lane >> 3) & 1) * 8;
    int ksel8 = (lane >> 4) * 8;

    float acc[4][4][4];
#pragma unroll
    for (int i = 0; i < 4; ++i)
#pragma unroll
        for (int f = 0; f < 4; ++f)
#pragma unroll
            for (int r = 0; r < 4; ++r) acc[i][f][r] = 0.f;

    int lrow = tid >> 3;   // 0..31
    int lq = tid & 7;      // 16B chunk (8 halves)

    auto load_tiles = [&](int buf, int k0) {
        const __half* Ag = A + (size_t)bm * K + k0;
        const __half* Bg = B + (size_t)bn * K + k0;
        __half* as = smh + buf * STAGE_SZ;
        __half* bs = as + GBM * HSTR;
#pragma unroll
        for (int p = 0; p < 4; ++p) {
            int r = lrow + p * 32;
            cp_async16(as + r * HSTR + lq * 8, Ag + (size_t)r * K + lq * 8);
        }
#pragma unroll
        for (int p = 0; p < 4; ++p) {
            int r = lrow + p * 32;
            cp_async16(bs + r * HSTR + lq * 8, Bg + (size_t)r * K + lq * 8);
        }
    };

    auto compute = [&](int buf) {
        const __half* as = smh + buf * STAGE_SZ;
        const __half* bs = as + GBM * HSTR;
#pragma unroll
        for (int ks = 0; ks < GBK / 16; ++ks) {
            int kb = ks * 16;
            unsigned af[4][4];
            unsigned bf[4][2];
#pragma unroll
            for (int i = 0; i < 4; ++i) {
                int rb = wm * 64 + i * 16;
                ldsm_x4(af[i][0], af[i][1], af[i][2], af[i][3],
                        &as[(rb + lm8 + lsel8) * HSTR + kb + ksel8]);
            }
#pragma unroll
            for (int fb = 0; fb < 2; ++fb) {
                int nb0 = wn * 32 + fb * 16;
                ldsm_x4(bf[2 * fb][0], bf[2 * fb + 1][0],
                        bf[2 * fb][1], bf[2 * fb + 1][1],
                        &bs[(nb0 + lm8 + lsel8) * HSTR + kb + ksel8]);
            }
#pragma unroll
            for (int i = 0; i < 4; ++i)
#pragma unroll
                for (int f = 0; f < 4; ++f) {
                    asm volatile(
                        "mma.sync.aligned.m16n8k16.row.col.f32.f16.f16.f32 "
                        "{%0,%1,%2,%3}, {%4,%5,%6,%7}, {%8,%9}, {%0,%1,%2,%3};"
                        : "+f"(acc[i][f][0]), "+f"(acc[i][f][1]),
                          "+f"(acc[i][f][2]), "+f"(acc[i][f][3])
                        : "r"(af[i][0]), "r"(af[i][1]), "r"(af[i][2]), "r"(af[i][3]),
                          "r"(bf[f][0]), "r"(bf[f][1]));
                }
        }
    };

    int NK = K / GBK;
    // prologue: fill 3 stages
#pragma unroll
    for (int s = 0; s < STAGES - 1; ++s) {
        int k0 = s * GBK; if (k0 > K - GBK) k0 = K - GBK;
        load_tiles(s, k0);
        asm volatile("cp.async.commit_group;\n");
    }

    for (int it = 0; it < NK; ++it) {
        asm volatile("cp.async.wait_group %0;\n" :: "n"(STAGES - 2));
        __syncthreads();
        compute(it & (STAGES - 1));
        // issue next stage (clamped redundant load on tail keeps group count uniform)
        int k0 = (it + STAGES - 1) * GBK;
        if (k0 > K - GBK) k0 = K - GBK;
        load_tiles((it + STAGES - 1) & (STAGES - 1), k0);
        asm volatile("cp.async.commit_group;\n");
    }

#pragma unroll
    for (int i = 0; i < 4; ++i) {
        int r0 = bm + wm * 64 + i * 16 + g;
#pragma unroll
        for (int f = 0; f < 4; ++f) {
            int col = bn + wn * 32 + f * 8 + 2 * c4;
            *(float2*)(C + (size_t)r0 * N + col) = make_float2(acc[i][f][0], acc[i][f][1]);
            *(float2*)(C + (size_t)(r0 + 8) * N + col) = make_float2(acc[i][f][2], acc[i][f][3]);
        }
    }
}

// ------------------------- layernorm + leaky_relu ---------------------------
__global__ __launch_bounds__(128) void ln_leaky_kernel(
    const float* __restrict__ Z, const float* __restrict__ bias,
    const float* __restrict__ g, const float* __restrict__ beta,
    float iscale, float* __restrict__ dstf, __half* __restrict__ dsth,
    float* __restrict__ xres)
{
    __shared__ float sh[8];
    int t = blockIdx.x;
    int tid = threadIdx.x;
    const float* row = Z + (size_t)t * D_DIM;

    float v[4];
    float s = 0.f;
#pragma unroll
    for (int q = 0; q < 4; ++q) {
        int idx = tid + q * 128;
        v[q] = row[idx] * iscale + bias[idx];
        s += v[q];
    }
#pragma unroll
    for (int off = 16; off > 0; off >>= 1) s += __shfl_xor_sync(0xffffffffu, s, off);
    if ((tid & 31) == 0) sh[tid >> 5] = s;
    __syncthreads();
    float mean = (sh[0] + sh[1] + sh[2] + sh[3]) * (1.f / D_DIM);

    float vs = 0.f;
#pragma unroll
    for (int q = 0; q < 4; ++q) { float d = v[q] - mean; vs += d * d; }
#pragma unroll
    for (int off = 16; off > 0; off >>= 1) vs += __shfl_xor_sync(0xffffffffu, vs, off);
    if ((tid & 31) == 0) sh[4 + (tid >> 5)] = vs;
    __syncthreads();
    float var = (sh[4] + sh[5] + sh[6] + sh[7]) * (1.f / D_DIM);
    float rstd = rsqrtf(var + 1e-5f);

#pragma unroll
    for (int q = 0; q < 4; ++q) {
        int idx = tid + q * 128;
        float y = (v[q] - mean) * rstd * g[idx] + beta[idx];
        y = (y > 0.f) ? y : 0.01f * y;
        if (dstf) dstf[(size_t)t * D_DIM + idx] = y;
        if (dsth) dsth[(size_t)t * D_DIM + idx] = __float2half_rn(y);
        if (xres) xres[(size_t)t * D_DIM + idx] += y;
    }
}

// ------------------------- launch ------------------------------------------
extern "C" void kernel_launch(void* const* d_in, const int* in_sizes, int n_in,
                              void* d_out, int out_size)
{
    const float* x     = (const float*)d_in[0];
    const float* state = (const float*)d_in[1];
    const unsigned int* start = (const unsigned int*)d_in[2];
    const float* Wtr   = (const float*)d_in[3];
    const float* Wc    = (const float*)d_in[4];
    const float* a     = (const float*)d_in[5];
    const float* b     = (const float*)d_in[6];
    const float* W0    = (const float*)d_in[7];
    const float* b0    = (const float*)d_in[8];
    const float* g0    = (const float*)d_in[9];
    const float* be0   = (const float*)d_in[10];
    const float* W1    = (const float*)d_in[11];
    const float* b1    = (const float*)d_in[12];
    const float* g1    = (const float*)d_in[13];
    const float* be1   = (const float*)d_in[14];
    float* out = (float*)d_out;

    float *pX, *pAtr, *pAct, *pInv, *pH, *pZ;
    __half *pScaledH, *pHH, *pW0h, *pW1h;
    cudaGetSymbolAddress((void**)&pX, g_X);
    cudaGetSymbolAddress((void**)&pAtr, g_atr);
    cudaGetSymbolAddress((void**)&pAct, g_act);
    cudaGetSymbolAddress((void**)&pInv, g_inv);
    cudaGetSymbolAddress((void**)&pScaledH, g_scaledh);
    cudaGetSymbolAddress((void**)&pH, g_h);
    cudaGetSymbolAddress((void**)&pHH, g_hh);
    cudaGetSymbolAddress((void**)&pZ, g_z);
    cudaGetSymbolAddress((void**)&pW0h, g_W0h);
    cudaGetSymbolAddress((void**)&pW1h, g_W1h);

    const int SMEM_GEMM = STAGES * (GBM + GBN) * HSTR * (int)sizeof(__half);  // 147456
    cudaFuncSetAttribute(gemm_f16, cudaFuncAttributeMaxDynamicSharedMemorySize, SMEM_GEMM);

    const int ND = T_LEN * D_DIM;
    copy_kernel<<<512, 256>>>(pX, x, ND);
    half_convert_kernel<<<1024, 256>>>(pW0h, W0, L_NUM * D_DIM * F_DIM, W0SCALE);
    half_convert_kernel<<<256, 256>>>(pW1h, W1, L_NUM * D_DIM * D_DIM, 1.0f);

    dim3 ggrid(D_DIM / GBN, T_LEN / GBM);   // (4, 32)
    dim3 sgrid(TR_DIM, NCH);                // (64, 64)

    for (int l = 0; l < L_NUM; ++l) {
        proj_gemm_kernel<<<T_LEN / PBM, 256>>>(
            pX, Wtr + (size_t)l * TR_DIM * D_DIM,
            Wc + (size_t)l * CC_DIM * D_DIM, pAtr, pAct, pInv);
        scan_chunkA_kernel<<<sgrid, 32>>>(
            pAtr, pAct, pInv, start,
            a + (size_t)l * TR_DIM, b + (size_t)l * CC_DIM);
        scan_combine_kernel<<<NCHAN / 256, 256>>>(
            state + (size_t)l * TR_DIM * CC_DIM);
        scan_chunkC_kernel<<<sgrid, 32>>>(
            pAtr, pAct, pInv, start,
            a + (size_t)l * TR_DIM, b + (size_t)l * CC_DIM, pScaledH);
        gemm_f16<<<ggrid, 256, SMEM_GEMM>>>(
            pScaledH, pW0h + (size_t)l * D_DIM * F_DIM, pH, T_LEN, D_DIM, F_DIM);
        ln_leaky_kernel<<<T_LEN, 128>>>(pH, b0 + (size_t)l * D_DIM,
                                        g0 + (size_t)l * D_DIM,
                                        be0 + (size_t)l * D_DIM,
                                        ISCALE0, nullptr, pHH, nullptr);
        gemm_f16<<<ggrid, 256, SMEM_GEMM>>>(
            pHH, pW1h + (size_t)l * D_DIM * D_DIM, pZ, T_LEN, D_DIM, D_DIM);
        if (l < L_NUM - 1) {
            ln_leaky_kernel<<<T_LEN, 128>>>(pZ, b1 + (size_t)l * D_DIM,
                                            g1 + (size_t)l * D_DIM,
                                            be1 + (size_t)l * D_DIM,
                                            1.0f, nullptr, nullptr, pX);
        } else {
            ln_leaky_kernel<<<T_LEN, 128>>>(pZ, b1 + (size_t)l * D_DIM,
                                            g1 + (size_t)l * D_DIM,
                                            be1 + (size_t)l * D_DIM,
                                            1.0f, out, nullptr, nullptr);
        }
    }
}

// round 10
// speedup vs baseline: 12.3382x; 1.0020x over previous
#include <cuda_runtime.h>
#include <cuda_bf16.h>
#include <cuda_fp16.h>
#include <math.h>

#define T_LEN 4096
#define D_DIM 512
#define TR_DIM 64
#define CC_DIM 64
#define F_DIM 8192   // 2*TR*CC
#define L_NUM 3
#define NCH 64       // scan chunks
#define CHUNK 64     // timesteps per chunk
#define NCHAN (TR_DIM * CC_DIM)

#define FSCALE 64.0f     // feature pre-scale (A of GEMM0)
#define W0SCALE 32.0f    // W0 pre-scale (B of GEMM0)
#define ISCALE0 (1.0f / (FSCALE * W0SCALE))

// ------------------------- scratch (device globals; no alloc) ---------------
__device__ float  g_X[(size_t)T_LEN * D_DIM];
__device__ float  g_atr[(size_t)T_LEN * TR_DIM];
__device__ float  g_act[(size_t)T_LEN * CC_DIM];
__device__ float  g_inv[T_LEN];
__device__ __half g_scaledh[(size_t)T_LEN * F_DIM];
__device__ float  g_h[(size_t)T_LEN * D_DIM];
__device__ __half g_hh[(size_t)T_LEN * D_DIM];
__device__ float  g_z[(size_t)T_LEN * D_DIM];
__device__ __half g_W0h[(size_t)L_NUM * D_DIM * F_DIM];
__device__ __half g_W1h[(size_t)L_NUM * D_DIM * D_DIM];
__device__ float  g_cAr[(size_t)NCH * NCHAN];
__device__ float  g_cAi[(size_t)NCH * NCHAN];
__device__ float  g_cBr[(size_t)NCH * NCHAN];
__device__ float  g_cBi[(size_t)NCH * NCHAN];
__device__ float  g_sinr[(size_t)NCH * NCHAN];
__device__ float  g_sini[(size_t)NCH * NCHAN];

__device__ __forceinline__ void cp_async16(void* smem_dst, const void* gsrc) {
    unsigned saddr = (unsigned)__cvta_generic_to_shared(smem_dst);
    asm volatile("cp.async.cg.shared.global [%0], [%1], 16;\n" :: "r"(saddr), "l"(gsrc));
}

__device__ __forceinline__ void ldsm_x4(unsigned& r0, unsigned& r1, unsigned& r2,
                                        unsigned& r3, const __half* p) {
    unsigned addr = (unsigned)__cvta_generic_to_shared(p);
    asm volatile("ldmatrix.sync.aligned.m8n8.x4.shared.b16 {%0,%1,%2,%3}, [%4];"
                 : "=r"(r0), "=r"(r1), "=r"(r2), "=r"(r3) : "r"(addr));
}

// ------------------------- small utility kernels ----------------------------
__global__ void copy_kernel(float* __restrict__ dst, const float* __restrict__ src, int n) {
    int i = blockIdx.x * blockDim.x + threadIdx.x;
    int stride = gridDim.x * blockDim.x;
    for (; i < n; i += stride) dst[i] = src[i];
}

__global__ void half_convert_kernel(__half* __restrict__ dst, const float* __restrict__ src,
                                    int n, float scale) {
    int i = blockIdx.x * blockDim.x + threadIdx.x;
    int stride = gridDim.x * blockDim.x;
    for (; i < n; i += stride) dst[i] = __float2half_rn(src[i] * scale);
}

// ------------------------- fused projection GEMM ----------------------------
// Block: 32 tokens x 128 outputs (64 tr + 64 ct), K=512. Grid = 128 blocks.
// Inner loop uses float4 smem fragment loads (xv broadcast, wv conflict-free).
#define PBM 32
#define PBK 32
__global__ __launch_bounds__(256) void proj_gemm_kernel(
    const float* __restrict__ X, const float* __restrict__ Wtr,
    const float* __restrict__ Wc, float* __restrict__ atr,
    float* __restrict__ act, float* __restrict__ inv)
{
    __shared__ float Xs[PBK][PBM + 4];
    __shared__ float Ws[PBK][128 + 4];
    __shared__ float red[PBM][2];

    int tid = threadIdx.x;
    int bm = blockIdx.x * PBM;
    int tx = tid & 31;    // output dir: 4 each
    int ty = tid >> 5;    // token dir:  4 each

    if (tid < 64) red[tid >> 1][tid & 1] = 0.f;

    float acc[4][4];
#pragma unroll
    for (int i = 0; i < 4; ++i)
#pragma unroll
        for (int j = 0; j < 4; ++j) acc[i][j] = 0.f;

    int lr = tid >> 3;   // 0..31
    int c4 = tid & 7;    // 0..7

    for (int k0 = 0; k0 < D_DIM; k0 += PBK) {
        // X tile 32x32: 256 float4, 1 per thread
        {
            float4 v = *(const float4*)(X + (size_t)(bm + lr) * D_DIM + k0 + c4 * 4);
            Xs[c4 * 4 + 0][lr] = v.x;
            Xs[c4 * 4 + 1][lr] = v.y;
            Xs[c4 * 4 + 2][lr] = v.z;
            Xs[c4 * 4 + 3][lr] = v.w;
        }
        // W tile 128x32: 1024 float4, 4 per thread
#pragma unroll
        for (int p = 0; p < 4; ++p) {
            int row = lr + p * 32;
            const float* Wrow = (row < 64) ? (Wtr + (size_t)row * D_DIM)
                                           : (Wc + (size_t)(row - 64) * D_DIM);
            float4 v = *(const float4*)(Wrow + k0 + c4 * 4);
            Ws[c4 * 4 + 0][row] = v.x;
            Ws[c4 * 4 + 1][row] = v.y;
            Ws[c4 * 4 + 2][row] = v.z;
            Ws[c4 * 4 + 3][row] = v.w;
        }
        __syncthreads();

#pragma unroll
        for (int kk = 0; kk < PBK; ++kk) {
            float4 xv = *(const float4*)&Xs[kk][ty * 4];   // broadcast within warp
            float4 wv = *(const float4*)&Ws[kk][tx * 4];   // 4-phase conflict-free
            float xa[4] = {xv.x, xv.y, xv.z, xv.w};
            float wa[4] = {wv.x, wv.y, wv.z, wv.w};
#pragma unroll
            for (int i = 0; i < 4; ++i)
#pragma unroll
                for (int j = 0; j < 4; ++j) acc[i][j] += xa[i] * wa[j];
        }
        __syncthreads();
    }

    int half_sel = (tx >= 16);
#pragma unroll
    for (int i = 0; i < 4; ++i) {
        int tok = ty * 4 + i;
        float psum = 0.f;
#pragma unroll
        for (int j = 0; j < 4; ++j) {
            float av = fabsf(acc[i][j]);
            psum += av;
            int o = tx * 4 + j;
            if (o < 64) atr[(size_t)(bm + tok) * TR_DIM + o] = av;
            else        act[(size_t)(bm + tok) * CC_DIM + o - 64] = av;
        }
        atomicAdd(&red[tok][half_sel], psum);
    }
    __syncthreads();
    if (tid < 32)
        inv[bm + tid] = 1.f / (1e-8f + red[tid][0] * red[tid][1]);
}

// ------------------------- scan pass A: chunk (A,B) --------------------------
__global__ __launch_bounds__(32) void scan_chunkA_kernel(
    const float* __restrict__ atr, const float* __restrict__ act,
    const float* __restrict__ inv, const unsigned int* __restrict__ start,
    const float* __restrict__ a, const float* __restrict__ b)
{
    __shared__ float ativ[CHUNK];
    __shared__ unsigned sfl[CHUNK];
    int i = blockIdx.x;
    int cidx = blockIdx.y;
    int tid = threadIdx.x;
    int t0 = cidx * CHUNK;

#pragma unroll
    for (int q = 0; q < 2; ++q) {
        int idx = tid + q * 32;
        int t = t0 + idx;
        ativ[idx] = atr[(size_t)t * TR_DIM + i] * inv[t];
        sfl[idx] = start[t];
    }
    __syncwarp();

    float mag = expf(-fabsf(a[i]));
    int j0 = tid, j1 = tid + 32;
    float b0 = b[j0], b1 = b[j1];
    float dr0 = mag * cosf(b0), di0 = mag * sinf(b0);
    float dr1 = mag * cosf(b1), di1 = mag * sinf(b1);

    float pr0 = dr0, pi0 = di0, pr1 = dr1, pi1 = di1;
#pragma unroll
    for (int q = 0; q < 6; ++q) {
        float n0r = pr0 * pr0 - pi0 * pi0, n0i = 2.f * pr0 * pi0;
        float n1r = pr1 * pr1 - pi1 * pi1, n1i = 2.f * pr1 * pi1;
        pr0 = n0r; pi0 = n0i; pr1 = n1r; pi1 = n1i;
    }

    float sr0 = 0.f, si0 = 0.f, sr1 = 0.f, si1 = 0.f;
    unsigned any = 0;

#pragma unroll 4
    for (int tt = 0; tt < CHUNK; ++tt) {
        float av = ativ[tt];
        unsigned st = sfl[tt];
        any |= st;
        const float* acp = act + (size_t)(t0 + tt) * CC_DIM;
        float p0 = av * acp[j0];
        float p1 = av * acp[j1];
        if (st) { sr0 = 0.f; si0 = 0.f; sr1 = 0.f; si1 = 0.f; }
        float n0r = sr0 * dr0 - si0 * di0 + p0;
        float n0i = sr0 * di0 + si0 * dr0;
        float n1r = sr1 * dr1 - si1 * di1 + p1;
        float n1i = sr1 * di1 + si1 * dr1;
        sr0 = n0r; si0 = n0i; sr1 = n1r; si1 = n1i;
    }

    size_t o0 = (size_t)cidx * NCHAN + i * CC_DIM + j0;
    size_t o1 = o0 + 32;
    float am = any ? 0.f : 1.f;
    g_cAr[o0] = am * pr0; g_cAi[o0] = am * pi0;
    g_cAr[o1] = am * pr1; g_cAi[o1] = am * pi1;
    g_cBr[o0] = sr0; g_cBi[o0] = si0;
    g_cBr[o1] = sr1; g_cBi[o1] = si1;
}

// ------------------------- scan pass B: combine chunks -----------------------
__global__ __launch_bounds__(256) void scan_combine_kernel(const float* __restrict__ st0)
{
    int ch = blockIdx.x * blockDim.x + threadIdx.x;
    if (ch >= NCHAN) return;
    float sr = st0[ch];
    float si = 0.f;
    for (int c = 0; c < NCH; ++c) {
        size_t o = (size_t)c * NCHAN + ch;
        g_sinr[o] = sr; g_sini[o] = si;
        float ar = g_cAr[o], ai = g_cAi[o];
        float nsr = sr * ar - si * ai + g_cBr[o];
        float nsi = sr * ai + si * ar + g_cBi[o];
        sr = nsr; si = nsi;
    }
}

// ------------------------- scan pass C: rescan + features --------------------
__device__ __forceinline__ float featf(float sr, float si) {
    float r2 = fmaxf(sr * sr + si * si, 1e-34f);
    float rr = rsqrtf(r2);
    float r = r2 * rr;
    float flog = __logf(1.f + r) * rr;
    float fpoly = 1.f - r * (0.5f - r * (1.f / 3.f));
    return (r < 0.03f) ? fpoly : flog;
}

__global__ __launch_bounds__(32) void scan_chunkC_kernel(
    const float* __restrict__ atr, const float* __restrict__ act,
    const float* __restrict__ inv, const unsigned int* __restrict__ start,
    const float* __restrict__ a, const float* __restrict__ b,
    __half* __restrict__ scaled)
{
    __shared__ float ativ[CHUNK];
    __shared__ unsigned sfl[CHUNK];
    int i = blockIdx.x;
    int cidx = blockIdx.y;
    int tid = threadIdx.x;
    int t0 = cidx * CHUNK;

#pragma unroll
    for (int q = 0; q < 2; ++q) {
        int idx = tid + q * 32;
        int t = t0 + idx;
        ativ[idx] = atr[(size_t)t * TR_DIM + i] * inv[t];
        sfl[idx] = start[t];
    }
    __syncwarp();

    float mag = expf(-fabsf(a[i]));
    int j0 = tid, j1 = tid + 32;
    float b0 = b[j0], b1 = b[j1];
    float dr0 = mag * cosf(b0), di0 = mag * sinf(b0);
    float dr1 = mag * cosf(b1), di1 = mag * sinf(b1);

    int ch0 = i * CC_DIM + j0;
    size_t o0 = (size_t)cidx * NCHAN + ch0;
    float sr0 = g_sinr[o0], si0 = g_sini[o0];
    float sr1 = g_sinr[o0 + 32], si1 = g_sini[o0 + 32];

#pragma unroll 2
    for (int tt = 0; tt < CHUNK; ++tt) {
        int t = t0 + tt;
        float av = ativ[tt];
        unsigned st = sfl[tt];
        const float* acp = act + (size_t)t * CC_DIM;
        float p0 = av * acp[j0];
        float p1 = av * acp[j1];
        if (st) { sr0 = 0.f; si0 = 0.f; sr1 = 0.f; si1 = 0.f; }
        float n0r = sr0 * dr0 - si0 * di0 + p0;
        float n0i = sr0 * di0 + si0 * dr0;
        float n1r = sr1 * dr1 - si1 * di1 + p1;
        float n1i = sr1 * di1 + si1 * dr1;
        sr0 = n0r; si0 = n0i; sr1 = n1r; si1 = n1i;

        float f0 = featf(sr0, si0) * FSCALE;
        float f1 = featf(sr1, si1) * FSCALE;
        __half* row = scaled + (size_t)t * F_DIM;
        row[ch0]              = __float2half_rn(f0 * si0);
        row[ch0 + 32]         = __float2half_rn(f1 * si1);
        row[ch0 + NCHAN]      = __float2half_rn(f0 * sr0);
        row[ch0 + 32 + NCHAN] = __float2half_rn(f1 * sr1);
    }
}

// ------------------------- FP16 tensor-core GEMM: C = A @ B^T ----------------
// A: MxK row-major __half, B: NxK row-major __half, C fp32.
// 64x128x64 CTA tile, 8 warps (2m x 4n), warp tile 32x32, mma.m16n8k16.
// 4-stage cp.async ring, ldmatrix fragment loads, 2 CTAs/SM.
#define GBM 64
#define GBN 128
#define GBK 64
#define STAGES 4
#define HSTR 72   // halves per smem row (64 + 8 pad) -> conflict-free ldmatrix

__global__ __launch_bounds__(256, 2) void gemm_f16(
    const __half* __restrict__ A, const __half* __restrict__ B,
    float* __restrict__ C, int M, int N, int K)
{
    extern __shared__ __half smh[];
    const int STAGE_SZ = (GBM + GBN) * HSTR;

    int tid = threadIdx.x;
    int bm = blockIdx.y * GBM, bn = blockIdx.x * GBN;
    int lane = tid & 31, wid = tid >> 5;
    int wm = wid & 1, wn = wid >> 1;           // 2 x 4 warp grid
    int g = lane >> 2, c4 = lane & 3;
    int lm8 = lane & 7;
    int lsel8 = ((lane >> 3) & 1) * 8;
    int ksel8 = (lane >> 4) * 8;

    float acc[2][4][4];
#pragma unroll
    for (int i = 0; i < 2; ++i)
#pragma unroll
        for (int f = 0; f < 4; ++f)
#pragma unroll
            for (int r = 0; r < 4; ++r) acc[i][f][r] = 0.f;

    int lrow = tid >> 3;   // 0..31
    int lq = tid & 7;      // 16B chunk (8 halves)

    auto load_tiles = [&](int buf, int k0) {
        const __half* Ag = A + (size_t)bm * K + k0;
        const __half* Bg = B + (size_t)bn * K + k0;
        __half* as = smh + buf * STAGE_SZ;
        __half* bs = as + GBM * HSTR;
#pragma unroll
        for (int p = 0; p < 2; ++p) {
            int r = lrow + p * 32;
            cp_async16(as + r * HSTR + lq * 8, Ag + (size_t)r * K + lq * 8);
        }
#pragma unroll
        for (int p = 0; p < 4; ++p) {
            int r = lrow + p * 32;
            cp_async16(bs + r * HSTR + lq * 8, Bg + (size_t)r * K + lq * 8);
        }
    };

    auto compute = [&](int buf) {
        const __half* as = smh + buf * STAGE_SZ;
        const __half* bs = as + GBM * HSTR;
#pragma unroll
        for (int ks = 0; ks < GBK / 16; ++ks) {
            int kb = ks * 16;
            unsigned af[2][4];
            unsigned bf[4][2];
#pragma unroll
            for (int i = 0; i < 2; ++i) {
                int rb = wm * 32 + i * 16;
                ldsm_x4(af[i][0], af[i][1], af[i][2], af[i][3],
                        &as[(rb + lm8 + lsel8) * HSTR + kb + ksel8]);
            }
#pragma unroll
            for (int fb = 0; fb < 2; ++fb) {
                int nb0 = wn * 32 + fb * 16;
                ldsm_x4(bf[2 * fb][0], bf[2 * fb + 1][0],
                        bf[2 * fb][1], bf[2 * fb + 1][1],
                        &bs[(nb0 + lm8 + lsel8) * HSTR + kb + ksel8]);
            }
#pragma unroll
            for (int i = 0; i < 2; ++i)
#pragma unroll
                for (int f = 0; f < 4; ++f) {
                    asm volatile(
                        "mma.sync.aligned.m16n8k16.row.col.f32.f16.f16.f32 "
                        "{%0,%1,%2,%3}, {%4,%5,%6,%7}, {%8,%9}, {%0,%1,%2,%3};"
                        : "+f"(acc[i][f][0]), "+f"(acc[i][f][1]),
                          "+f"(acc[i][f][2]), "+f"(acc[i][f][3])
                        : "r"(af[i][0]), "r"(af[i][1]), "r"(af[i][2]), "r"(af[i][3]),
                          "r"(bf[f][0]), "r"(bf[f][1]));
                }
        }
    };

    int NK = K / GBK;
    // prologue: fill STAGES-1 stages
#pragma unroll
    for (int s = 0; s < STAGES - 1; ++s) {
        int k0 = s * GBK; if (k0 > K - GBK) k0 = K - GBK;
        load_tiles(s, k0);
        asm volatile("cp.async.commit_group;\n");
    }

    for (int it = 0; it < NK; ++it) {
        asm volatile("cp.async.wait_group %0;\n" :: "n"(STAGES - 2));
        __syncthreads();
        compute(it & (STAGES - 1));
        int k0 = (it + STAGES - 1) * GBK;
        if (k0 > K - GBK) k0 = K - GBK;
        load_tiles((it + STAGES - 1) & (STAGES - 1), k0);
        asm volatile("cp.async.commit_group;\n");
    }

#pragma unroll
    for (int i = 0; i < 2; ++i) {
        int r0 = bm + wm * 32 + i * 16 + g;
#pragma unroll
        for (int f = 0; f < 4; ++f) {
            int col = bn + wn * 32 + f * 8 + 2 * c4;
            *(float2*)(C + (size_t)r0 * N + col) = make_float2(acc[i][f][0], acc[i][f][1]);
            *(float2*)(C + (size_t)(r0 + 8) * N + col) = make_float2(acc[i][f][2], acc[i][f][3]);
        }
    }
}

// ------------------------- layernorm + leaky_relu ---------------------------
__global__ __launch_bounds__(128) void ln_leaky_kernel(
    const float* __restrict__ Z, const float* __restrict__ bias,
    const float* __restrict__ g, const float* __restrict__ beta,
    float iscale, float* __restrict__ dstf, __half* __restrict__ dsth,
    float* __restrict__ xres)
{
    __shared__ float sh[8];
    int t = blockIdx.x;
    int tid = threadIdx.x;
    const float* row = Z + (size_t)t * D_DIM;

    float v[4];
    float s = 0.f;
#pragma unroll
    for (int q = 0; q < 4; ++q) {
        int idx = tid + q * 128;
        v[q] = row[idx] * iscale + bias[idx];
        s += v[q];
    }
#pragma unroll
    for (int off = 16; off > 0; off >>= 1) s += __shfl_xor_sync(0xffffffffu, s, off);
    if ((tid & 31) == 0) sh[tid >> 5] = s;
    __syncthreads();
    float mean = (sh[0] + sh[1] + sh[2] + sh[3]) * (1.f / D_DIM);

    float vs = 0.f;
#pragma unroll
    for (int q = 0; q < 4; ++q) { float d = v[q] - mean; vs += d * d; }
#pragma unroll
    for (int off = 16; off > 0; off >>= 1) vs += __shfl_xor_sync(0xffffffffu, vs, off);
    if ((tid & 31) == 0) sh[4 + (tid >> 5)] = vs;
    __syncthreads();
    float var = (sh[4] + sh[5] + sh[6] + sh[7]) * (1.f / D_DIM);
    float rstd = rsqrtf(var + 1e-5f);

#pragma unroll
    for (int q = 0; q < 4; ++q) {
        int idx = tid + q * 128;
        float y = (v[q] - mean) * rstd * g[idx] + beta[idx];
        y = (y > 0.f) ? y : 0.01f * y;
        if (dstf) dstf[(size_t)t * D_DIM + idx] = y;
        if (dsth) dsth[(size_t)t * D_DIM + idx] = __float2half_rn(y);
        if (xres) xres[(size_t)t * D_DIM + idx] += y;
    }
}

// ------------------------- launch ------------------------------------------
extern "C" void kernel_launch(void* const* d_in, const int* in_sizes, int n_in,
                              void* d_out, int out_size)
{
    const float* x     = (const float*)d_in[0];
    const float* state = (const float*)d_in[1];
    const unsigned int* start = (const unsigned int*)d_in[2];
    const float* Wtr   = (const float*)d_in[3];
    const float* Wc    = (const float*)d_in[4];
    const float* a     = (const float*)d_in[5];
    const float* b     = (const float*)d_in[6];
    const float* W0    = (const float*)d_in[7];
    const float* b0    = (const float*)d_in[8];
    const float* g0    = (const float*)d_in[9];
    const float* be0   = (const float*)d_in[10];
    const float* W1    = (const float*)d_in[11];
    const float* b1    = (const float*)d_in[12];
    const float* g1    = (const float*)d_in[13];
    const float* be1   = (const float*)d_in[14];
    float* out = (float*)d_out;

    float *pX, *pAtr, *pAct, *pInv, *pH, *pZ;
    __half *pScaledH, *pHH, *pW0h, *pW1h;
    cudaGetSymbolAddress((void**)&pX, g_X);
    cudaGetSymbolAddress((void**)&pAtr, g_atr);
    cudaGetSymbolAddress((void**)&pAct, g_act);
    cudaGetSymbolAddress((void**)&pInv, g_inv);
    cudaGetSymbolAddress((void**)&pScaledH, g_scaledh);
    cudaGetSymbolAddress((void**)&pH, g_h);
    cudaGetSymbolAddress((void**)&pHH, g_hh);
    cudaGetSymbolAddress((void**)&pZ, g_z);
    cudaGetSymbolAddress((void**)&pW0h, g_W0h);
    cudaGetSymbolAddress((void**)&pW1h, g_W1h);

    const int SMEM_GEMM = STAGES * (GBM + GBN) * HSTR * (int)sizeof(__half);  // 110592
    cudaFuncSetAttribute(gemm_f16, cudaFuncAttributeMaxDynamicSharedMemorySize, SMEM_GEMM);

    const int ND = T_LEN * D_DIM;
    copy_kernel<<<512, 256>>>(pX, x, ND);
    half_convert_kernel<<<1024, 256>>>(pW0h, W0, L_NUM * D_DIM * F_DIM, W0SCALE);
    half_convert_kernel<<<256, 256>>>(pW1h, W1, L_NUM * D_DIM * D_DIM, 1.0f);

    dim3 ggrid(D_DIM / GBN, T_LEN / GBM);   // (4, 64) = 256 CTAs
    dim3 sgrid(TR_DIM, NCH);                // (64, 64)

    for (int l = 0; l < L_NUM; ++l) {
        proj_gemm_kernel<<<T_LEN / PBM, 256>>>(
            pX, Wtr + (size_t)l * TR_DIM * D_DIM,
            Wc + (size_t)l * CC_DIM * D_DIM, pAtr, pAct, pInv);
        scan_chunkA_kernel<<<sgrid, 32>>>(
            pAtr, pAct, pInv, start,
            a + (size_t)l * TR_DIM, b + (size_t)l * CC_DIM);
        scan_combine_kernel<<<NCHAN / 256, 256>>>(
            state + (size_t)l * TR_DIM * CC_DIM);
        scan_chunkC_kernel<<<sgrid, 32>>>(
            pAtr, pAct, pInv, start,
            a + (size_t)l * TR_DIM, b + (size_t)l * CC_DIM, pScaledH);
        gemm_f16<<<ggrid, 256, SMEM_GEMM>>>(
            pScaledH, pW0h + (size_t)l * D_DIM * F_DIM, pH, T_LEN, D_DIM, F_DIM);
        ln_leaky_kernel<<<T_LEN, 128>>>(pH, b0 + (size_t)l * D_DIM,
                                        g0 + (size_t)l * D_DIM,
                                        be0 + (size_t)l * D_DIM,
                                        ISCALE0, nullptr, pHH, nullptr);
        gemm_f16<<<ggrid, 256, SMEM_GEMM>>>(
            pHH, pW1h + (size_t)l * D_DIM * D_DIM, pZ, T_LEN, D_DIM, D_DIM);
        if (l < L_NUM - 1) {
            ln_leaky_kernel<<<T_LEN, 128>>>(pZ, b1 + (size_t)l * D_DIM,
                                            g1 + (size_t)l * D_DIM,
                                            be1 + (size_t)l * D_DIM,
                                            1.0f, nullptr, nullptr, pX);
        } else {
            ln_leaky_kernel<<<T_LEN, 128>>>(pZ, b1 + (size_t)l * D_DIM,
                                            g1 + (size_t)l * D_DIM,
                                            be1 + (size_t)l * D_DIM,
                                            1.0f, out, nullptr, nullptr);
        }
    }
}

// round 15
// speedup vs baseline: 12.4409x; 1.0083x over previous
#include <cuda_runtime.h>
#include <cuda_bf16.h>
#include <cuda_fp16.h>
#include <math.h>

#define T_LEN 4096
#define D_DIM 512
#define TR_DIM 64
#define CC_DIM 64
#define F_DIM 8192   // 2*TR*CC
#define L_NUM 3
#define NCH 64       // scan chunks
#define CHUNK 64     // timesteps per chunk
#define NCHAN (TR_DIM * CC_DIM)

#define FSCALE 64.0f     // feature pre-scale (A of GEMM0)
#define W0SCALE 32.0f    // W0 pre-scale (B of GEMM0)
#define ISCALE0 (1.0f / (FSCALE * W0SCALE))

// ------------------------- scratch (device globals; no alloc) ---------------
__device__ float  g_X[(size_t)T_LEN * D_DIM];
__device__ float  g_atr[(size_t)T_LEN * TR_DIM];
__device__ float  g_act[(size_t)T_LEN * CC_DIM];
__device__ float  g_inv[T_LEN];
__device__ float  g_p0[(size_t)T_LEN * 128];     // proj partial (k-half 0)
__device__ float  g_p1[(size_t)T_LEN * 128];     // proj partial (k-half 1)
__device__ __half g_scaledh[(size_t)T_LEN * F_DIM];
__device__ float  g_h[(size_t)T_LEN * D_DIM];
__device__ __half g_hh[(size_t)T_LEN * D_DIM];
__device__ float  g_z[(size_t)T_LEN * D_DIM];
__device__ __half g_W0h[(size_t)L_NUM * D_DIM * F_DIM];
__device__ __half g_W1h[(size_t)L_NUM * D_DIM * D_DIM];

__device__ __forceinline__ void cp_async16(void* smem_dst, const void* gsrc) {
    unsigned saddr = (unsigned)__cvta_generic_to_shared(smem_dst);
    asm volatile("cp.async.cg.shared.global [%0], [%1], 16;\n" :: "r"(saddr), "l"(gsrc));
}

__device__ __forceinline__ void ldsm_x4(unsigned& r0, unsigned& r1, unsigned& r2,
                                        unsigned& r3, const __half* p) {
    unsigned addr = (unsigned)__cvta_generic_to_shared(p);
    asm volatile("ldmatrix.sync.aligned.m8n8.x4.shared.b16 {%0,%1,%2,%3}, [%4];"
                 : "=r"(r0), "=r"(r1), "=r"(r2), "=r"(r3) : "r"(addr));
}

// ------------------------- small utility kernels ----------------------------
__global__ void copy_kernel(float* __restrict__ dst, const float* __restrict__ src, int n) {
    int i = blockIdx.x * blockDim.x + threadIdx.x;
    int stride = gridDim.x * blockDim.x;
    for (; i < n; i += stride) dst[i] = src[i];
}

__global__ void half_convert_kernel(__half* __restrict__ dst, const float* __restrict__ src,
                                    int n, float scale) {
    int i = blockIdx.x * blockDim.x + threadIdx.x;
    int stride = gridDim.x * blockDim.x;
    for (; i < n; i += stride) dst[i] = __float2half_rn(src[i] * scale);
}

// ------------------------- projection GEMM (split-K) -------------------------
// Block: 32 tokens x 128 outputs, K = 256 (blockIdx.y selects k-half).
// Grid (128, 2). Writes raw partial sums to g_p0 / g_p1.
#define PBM 32
#define PBK 32
__global__ __launch_bounds__(256) void proj_gemm_kernel(
    const float* __restrict__ X, const float* __restrict__ Wtr,
    const float* __restrict__ Wc)
{
    __shared__ float Xs[PBK][PBM + 4];
    __shared__ float Ws[PBK][128 + 4];

    int tid = threadIdx.x;
    int bm = blockIdx.x * PBM;
    int kbase = blockIdx.y * (D_DIM / 2);
    float* part = blockIdx.y ? g_p1 : g_p0;
    int tx = tid & 31;    // output dir: 4 each
    int ty = tid >> 5;    // token dir:  4 each

    float acc[4][4];
#pragma unroll
    for (int i = 0; i < 4; ++i)
#pragma unroll
        for (int j = 0; j < 4; ++j) acc[i][j] = 0.f;

    int lr = tid >> 3;   // 0..31
    int c4 = tid & 7;    // 0..7

    for (int k0 = kbase; k0 < kbase + D_DIM / 2; k0 += PBK) {
        {
            float4 v = *(const float4*)(X + (size_t)(bm + lr) * D_DIM + k0 + c4 * 4);
            Xs[c4 * 4 + 0][lr] = v.x;
            Xs[c4 * 4 + 1][lr] = v.y;
            Xs[c4 * 4 + 2][lr] = v.z;
            Xs[c4 * 4 + 3][lr] = v.w;
        }
#pragma unroll
        for (int p = 0; p < 4; ++p) {
            int row = lr + p * 32;
            const float* Wrow = (row < 64) ? (Wtr + (size_t)row * D_DIM)
                                           : (Wc + (size_t)(row - 64) * D_DIM);
            float4 v = *(const float4*)(Wrow + k0 + c4 * 4);
            Ws[c4 * 4 + 0][row] = v.x;
            Ws[c4 * 4 + 1][row] = v.y;
            Ws[c4 * 4 + 2][row] = v.z;
            Ws[c4 * 4 + 3][row] = v.w;
        }
        __syncthreads();

#pragma unroll
        for (int kk = 0; kk < PBK; ++kk) {
            float4 xv = *(const float4*)&Xs[kk][ty * 4];
            float4 wv = *(const float4*)&Ws[kk][tx * 4];
            float xa[4] = {xv.x, xv.y, xv.z, xv.w};
            float wa[4] = {wv.x, wv.y, wv.z, wv.w};
#pragma unroll
            for (int i = 0; i < 4; ++i)
#pragma unroll
                for (int j = 0; j < 4; ++j) acc[i][j] += xa[i] * wa[j];
        }
        __syncthreads();
    }

#pragma unroll
    for (int i = 0; i < 4; ++i) {
        int tok = bm + ty * 4 + i;
        *(float4*)(part + (size_t)tok * 128 + tx * 4) =
            make_float4(acc[i][0], acc[i][1], acc[i][2], acc[i][3]);
    }
}

// ------------------------- proj merge: add halves, abs, row sums, inv --------
__global__ __launch_bounds__(256) void proj_merge_kernel(
    float* __restrict__ atr, float* __restrict__ act, float* __restrict__ inv)
{
    __shared__ float red[PBM][2];
    int tid = threadIdx.x;
    int bm = blockIdx.x * PBM;
    int tx = tid & 31;
    int ty = tid >> 5;

    if (tid < 64) red[tid >> 1][tid & 1] = 0.f;
    __syncthreads();

    int half_sel = (tx >= 16);
#pragma unroll
    for (int i = 0; i < 4; ++i) {
        int tok = bm + ty * 4 + i;
        float4 v0 = *(const float4*)(g_p0 + (size_t)tok * 128 + tx * 4);
        float4 v1 = *(const float4*)(g_p1 + (size_t)tok * 128 + tx * 4);
        float av[4] = { fabsf(v0.x + v1.x), fabsf(v0.y + v1.y),
                        fabsf(v0.z + v1.z), fabsf(v0.w + v1.w) };
        float psum = av[0] + av[1] + av[2] + av[3];
#pragma unroll
        for (int j = 0; j < 4; ++j) {
            int o = tx * 4 + j;
            if (o < 64) atr[(size_t)tok * TR_DIM + o] = av[j];
            else        act[(size_t)tok * CC_DIM + o - 64] = av[j];
        }
        atomicAdd(&red[ty * 4 + i][half_sel], psum);
    }
    __syncthreads();
    if (tid < 32)
        inv[bm + tid] = 1.f / (1e-8f + red[tid][0] * red[tid][1]);
}

// ------------------------- fused segmented scan (A + combine + C) ------------
// Grid = TR_DIM (one CTA per i), 1024 threads = 32 warps; warp w owns chunks
// 2w, 2w+1. All chunk state lives in dynamic smem; combine runs on 64 threads.
__device__ __forceinline__ float featf(float sr, float si) {
    float r2 = fmaxf(sr * sr + si * si, 1e-34f);
    float rr = rsqrtf(r2);
    float r = r2 * rr;
    float flog = __logf(1.f + r) * rr;
    float fpoly = 1.f - r * (0.5f - r * (1.f / 3.f));
    return (r < 0.03f) ? fpoly : flog;
}

#define SCAN_SMEM_BYTES (5 * T_LEN * 4 + T_LEN + NCH * 4 + 256)

__global__ __launch_bounds__(1024, 1) void scan_fused_kernel(
    const float* __restrict__ atr, const float* __restrict__ act,
    const float* __restrict__ inv, const unsigned int* __restrict__ start,
    const float* __restrict__ a, const float* __restrict__ b,
    const float* __restrict__ st0, __half* __restrict__ scaled)
{
    extern __shared__ float sfm[];
    float* ativ = sfm;                        // [T_LEN]
    float* Bre  = ativ + T_LEN;               // [NCH*64]
    float* Bim  = Bre + NCH * 64;             // [NCH*64]
    float* Sre  = Bim + NCH * 64;             // [NCH*64]
    float* Sim  = Sre + NCH * 64;             // [NCH*64]
    unsigned char* sfl = (unsigned char*)(Sim + NCH * 64);  // [T_LEN]
    unsigned* anyst = (unsigned*)(sfl + T_LEN);             // [NCH]

    int i = blockIdx.x;
    int tid = threadIdx.x;
    int lane = tid & 31, w = tid >> 5;

    // stage at*inv and start flags for all t
#pragma unroll
    for (int q = 0; q < 4; ++q) {
        int t = tid + q * 1024;
        ativ[t] = atr[(size_t)t * TR_DIM + i] * inv[t];
        sfl[t] = (unsigned char)(start[t] != 0u);
    }
    __syncthreads();

    float mag = expf(-fabsf(a[i]));
    int j0 = lane, j1 = lane + 32;
    float b0v = b[j0], b1v = b[j1];
    float dr0 = mag * cosf(b0v), di0 = mag * sinf(b0v);
    float dr1 = mag * cosf(b1v), di1 = mag * sinf(b1v);

    // ---- pass A: per-chunk local scans from zero ----
#pragma unroll
    for (int cc = 0; cc < 2; ++cc) {
        int c = 2 * w + cc;
        int t0 = c * CHUNK;
        float sr0 = 0.f, si0 = 0.f, sr1 = 0.f, si1 = 0.f;
        unsigned any = 0;
#pragma unroll 4
        for (int tt = 0; tt < CHUNK; ++tt) {
            int t = t0 + tt;
            float av = ativ[t];
            unsigned st = sfl[t];
            any |= st;
            const float* acp = act + (size_t)t * CC_DIM;
            float p0 = av * acp[j0];
            float p1 = av * acp[j1];
            if (st) { sr0 = 0.f; si0 = 0.f; sr1 = 0.f; si1 = 0.f; }
            float n0r = sr0 * dr0 - si0 * di0 + p0;
            float n0i = sr0 * di0 + si0 * dr0;
            float n1r = sr1 * dr1 - si1 * di1 + p1;
            float n1i = sr1 * di1 + si1 * dr1;
            sr0 = n0r; si0 = n0i; sr1 = n1r; si1 = n1i;
        }
        Bre[c * 64 + j0] = sr0; Bim[c * 64 + j0] = si0;
        Bre[c * 64 + j1] = sr1; Bim[c * 64 + j1] = si1;
        if (lane == 0) anyst[c] = any;
    }
    __syncthreads();

    // ---- combine: 64 threads, one channel j each, serial over chunks ----
    if (tid < 64) {
        int j = tid;
        float bj = b[j];
        float ddr = mag * cosf(bj), ddi = mag * sinf(bj);
        float dpr = ddr, dpi = ddi;   // d^CHUNK via 6 squarings
#pragma unroll
        for (int q = 0; q < 6; ++q) {
            float nr = dpr * dpr - dpi * dpi;
            float ni = 2.f * dpr * dpi;
            dpr = nr; dpi = ni;
        }
        float sr = st0[i * CC_DIM + j];
        float si = 0.f;
        for (int c = 0; c < NCH; ++c) {
            Sre[c * 64 + j] = sr; Sim[c * 64 + j] = si;
            float ar = anyst[c] ? 0.f : dpr;
            float ai = anyst[c] ? 0.f : dpi;
            float nsr = sr * ar - si * ai + Bre[c * 64 + j];
            float nsi = sr * ai + si * ar + Bim[c * 64 + j];
            sr = nsr; si = nsi;
        }
    }
    __syncthreads();

    // ---- pass C: rescan with incoming states + feature map ----
#pragma unroll
    for (int cc = 0; cc < 2; ++cc) {
        int c = 2 * w + cc;
        int t0 = c * CHUNK;
        int ch0 = i * CC_DIM + j0;
        float sr0 = Sre[c * 64 + j0], si0 = Sim[c * 64 + j0];
        float sr1 = Sre[c * 64 + j1], si1 = Sim[c * 64 + j1];
#pragma unroll 2
        for (int tt = 0; tt < CHUNK; ++tt) {
            int t = t0 + tt;
            float av = ativ[t];
            unsigned st = sfl[t];
            const float* acp = act + (size_t)t * CC_DIM;
            float p0 = av * acp[j0];
            float p1 = av * acp[j1];
            if (st) { sr0 = 0.f; si0 = 0.f; sr1 = 0.f; si1 = 0.f; }
            float n0r = sr0 * dr0 - si0 * di0 + p0;
            float n0i = sr0 * di0 + si0 * dr0;
            float n1r = sr1 * dr1 - si1 * di1 + p1;
            float n1i = sr1 * di1 + si1 * dr1;
            sr0 = n0r; si0 = n0i; sr1 = n1r; si1 = n1i;

            float f0 = featf(sr0, si0) * FSCALE;
            float f1 = featf(sr1, si1) * FSCALE;
            __half* row = scaled + (size_t)t * F_DIM;
            row[ch0]              = __float2half_rn(f0 * si0);
            row[ch0 + 32]         = __float2half_rn(f1 * si1);
            row[ch0 + NCHAN]      = __float2half_rn(f0 * sr0);
            row[ch0 + 32 + NCHAN] = __float2half_rn(f1 * sr1);
        }
    }
}

// ------------------------- FP16 tensor-core GEMM: C = A @ B^T ----------------
#define GBM 64
#define GBN 128
#define GBK 64
#define STAGES 4
#define HSTR 72

__global__ __launch_bounds__(256, 2) void gemm_f16(
    const __half* __restrict__ A, const __half* __restrict__ B,
    float* __restrict__ C, int M, int N, int K)
{
    extern __shared__ __half smh[];
    const int STAGE_SZ = (GBM + GBN) * HSTR;

    int tid = threadIdx.x;
    int bm = blockIdx.y * GBM, bn = blockIdx.x * GBN;
    int lane = tid & 31, wid = tid >> 5;
    int wm = wid & 1, wn = wid >> 1;
    int g = lane >> 2, c4 = lane & 3;
    int lm8 = lane & 7;
    int lsel8 = ((lane >> 3) & 1) * 8;
    int ksel8 = (lane >> 4) * 8;

    float acc[2][4][4];
#pragma unroll
    for (int i = 0; i < 2; ++i)
#pragma unroll
        for (int f = 0; f < 4; ++f)
#pragma unroll
            for (int r = 0; r < 4; ++r) acc[i][f][r] = 0.f;

    int lrow = tid >> 3;
    int lq = tid & 7;

    auto load_tiles = [&](int buf, int k0) {
        const __half* Ag = A + (size_t)bm * K + k0;
        const __half* Bg = B + (size_t)bn * K + k0;
        __half* as = smh + buf * STAGE_SZ;
        __half* bs = as + GBM * HSTR;
#pragma unroll
        for (int p = 0; p < 2; ++p) {
            int r = lrow + p * 32;
            cp_async16(as + r * HSTR + lq * 8, Ag + (size_t)r * K + lq * 8);
        }
#pragma unroll
        for (int p = 0; p < 4; ++p) {
            int r = lrow + p * 32;
            cp_async16(bs + r * HSTR + lq * 8, Bg + (size_t)r * K + lq * 8);
        }
    };

    auto compute = [&](int buf) {
        const __half* as = smh + buf * STAGE_SZ;
        const __half* bs = as + GBM * HSTR;
#pragma unroll
        for (int ks = 0; ks < GBK / 16; ++ks) {
            int kb = ks * 16;
            unsigned af[2][4];
            unsigned bf[4][2];
#pragma unroll
            for (int i = 0; i < 2; ++i) {
                int rb = wm * 32 + i * 16;
                ldsm_x4(af[i][0], af[i][1], af[i][2], af[i][3],
                        &as[(rb + lm8 + lsel8) * HSTR + kb + ksel8]);
            }
#pragma unroll
            for (int fb = 0; fb < 2; ++fb) {
                int nb0 = wn * 32 + fb * 16;
                ldsm_x4(bf[2 * fb][0], bf[2 * fb + 1][0],
                        bf[2 * fb][1], bf[2 * fb + 1][1],
                        &bs[(nb0 + lm8 + lsel8) * HSTR + kb + ksel8]);
            }
#pragma unroll
            for (int i = 0; i < 2; ++i)
#pragma unroll
                for (int f = 0; f < 4; ++f) {
                    asm volatile(
                        "mma.sync.aligned.m16n8k16.row.col.f32.f16.f16.f32 "
                        "{%0,%1,%2,%3}, {%4,%5,%6,%7}, {%8,%9}, {%0,%1,%2,%3};"
                        : "+f"(acc[i][f][0]), "+f"(acc[i][f][1]),
                          "+f"(acc[i][f][2]), "+f"(acc[i][f][3])
                        : "r"(af[i][0]), "r"(af[i][1]), "r"(af[i][2]), "r"(af[i][3]),
                          "r"(bf[f][0]), "r"(bf[f][1]));
                }
        }
    };

    int NK = K / GBK;
#pragma unroll
    for (int s = 0; s < STAGES - 1; ++s) {
        int k0 = s * GBK; if (k0 > K - GBK) k0 = K - GBK;
        load_tiles(s, k0);
        asm volatile("cp.async.commit_group;\n");
    }

    for (int it = 0; it < NK; ++it) {
        asm volatile("cp.async.wait_group %0;\n" :: "n"(STAGES - 2));
        __syncthreads();
        compute(it & (STAGES - 1));
        int k0 = (it + STAGES - 1) * GBK;
        if (k0 > K - GBK) k0 = K - GBK;
        load_tiles((it + STAGES - 1) & (STAGES - 1), k0);
        asm volatile("cp.async.commit_group;\n");
    }

#pragma unroll
    for (int i = 0; i < 2; ++i) {
        int r0 = bm + wm * 32 + i * 16 + g;
#pragma unroll
        for (int f = 0; f < 4; ++f) {
            int col = bn + wn * 32 + f * 8 + 2 * c4;
            *(float2*)(C + (size_t)r0 * N + col) = make_float2(acc[i][f][0], acc[i][f][1]);
            *(float2*)(C + (size_t)(r0 + 8) * N + col) = make_float2(acc[i][f][2], acc[i][f][3]);
        }
    }
}

// ------------------------- layernorm + leaky_relu ---------------------------
__global__ __launch_bounds__(128) void ln_leaky_kernel(
    const float* __restrict__ Z, const float* __restrict__ bias,
    const float* __restrict__ g, const float* __restrict__ beta,
    float iscale, float* __restrict__ dstf, __half* __restrict__ dsth,
    float* __restrict__ xres)
{
    __shared__ float sh[8];
    int t = blockIdx.x;
    int tid = threadIdx.x;
    const float* row = Z + (size_t)t * D_DIM;

    float v[4];
    float s = 0.f;
#pragma unroll
    for (int q = 0; q < 4; ++q) {
        int idx = tid + q * 128;
        v[q] = row[idx] * iscale + bias[idx];
        s += v[q];
    }
#pragma unroll
    for (int off = 16; off > 0; off >>= 1) s += __shfl_xor_sync(0xffffffffu, s, off);
    if ((tid & 31) == 0) sh[tid >> 5] = s;
    __syncthreads();
    float mean = (sh[0] + sh[1] + sh[2] + sh[3]) * (1.f / D_DIM);

    float vs = 0.f;
#pragma unroll
    for (int q = 0; q < 4; ++q) { float d = v[q] - mean; vs += d * d; }
#pragma unroll
    for (int off = 16; off > 0; off >>= 1) vs += __shfl_xor_sync(0xffffffffu, vs, off);
    if ((tid & 31) == 0) sh[4 + (tid >> 5)] = vs;
    __syncthreads();
    float var = (sh[4] + sh[5] + sh[6] + sh[7]) * (1.f / D_DIM);
    float rstd = rsqrtf(var + 1e-5f);

#pragma unroll
    for (int q = 0; q < 4; ++q) {
        int idx = tid + q * 128;
        float y = (v[q] - mean) * rstd * g[idx] + beta[idx];
        y = (y > 0.f) ? y : 0.01f * y;
        if (dstf) dstf[(size_t)t * D_DIM + idx] = y;
        if (dsth) dsth[(size_t)t * D_DIM + idx] = __float2half_rn(y);
        if (xres) xres[(size_t)t * D_DIM + idx] += y;
    }
}

// ------------------------- launch ------------------------------------------
extern "C" void kernel_launch(void* const* d_in, const int* in_sizes, int n_in,
                              void* d_out, int out_size)
{
    const float* x     = (const float*)d_in[0];
    const float* state = (const float*)d_in[1];
    const unsigned int* start = (const unsigned int*)d_in[2];
    const float* Wtr   = (const float*)d_in[3];
    const float* Wc    = (const float*)d_in[4];
    const float* a     = (const float*)d_in[5];
    const float* b     = (const float*)d_in[6];
    const float* W0    = (const float*)d_in[7];
    const float* b0    = (const float*)d_in[8];
    const float* g0    = (const float*)d_in[9];
    const float* be0   = (const float*)d_in[10];
    const float* W1    = (const float*)d_in[11];
    const float* b1    = (const float*)d_in[12];
    const float* g1    = (const float*)d_in[13];
    const float* be1   = (const float*)d_in[14];
    float* out = (float*)d_out;

    float *pX, *pAtr, *pAct, *pInv, *pH, *pZ;
    __half *pScaledH, *pHH, *pW0h, *pW1h;
    cudaGetSymbolAddress((void**)&pX, g_X);
    cudaGetSymbolAddress((void**)&pAtr, g_atr);
    cudaGetSymbolAddress((void**)&pAct, g_act);
    cudaGetSymbolAddress((void**)&pInv, g_inv);
    cudaGetSymbolAddress((void**)&pScaledH, g_scaledh);
    cudaGetSymbolAddress((void**)&pH, g_h);
    cudaGetSymbolAddress((void**)&pHH, g_hh);
    cudaGetSymbolAddress((void**)&pZ, g_z);
    cudaGetSymbolAddress((void**)&pW0h, g_W0h);
    cudaGetSymbolAddress((void**)&pW1h, g_W1h);

    const int SMEM_GEMM = STAGES * (GBM + GBN) * HSTR * (int)sizeof(__half);  // 110592
    cudaFuncSetAttribute(gemm_f16, cudaFuncAttributeMaxDynamicSharedMemorySize, SMEM_GEMM);
    cudaFuncSetAttribute(scan_fused_kernel, cudaFuncAttributeMaxDynamicSharedMemorySize,
                         SCAN_SMEM_BYTES);

    const int ND = T_LEN * D_DIM;
    copy_kernel<<<512, 256>>>(pX, x, ND);
    half_convert_kernel<<<1024, 256>>>(pW0h, W0, L_NUM * D_DIM * F_DIM, W0SCALE);
    half_convert_kernel<<<256, 256>>>(pW1h, W1, L_NUM * D_DIM * D_DIM, 1.0f);

    dim3 ggrid(D_DIM / GBN, T_LEN / GBM);   // (4, 64)
    dim3 pgrid(T_LEN / PBM, 2);             // (128, 2) split-K

    for (int l = 0; l < L_NUM; ++l) {
        proj_gemm_kernel<<<pgrid, 256>>>(
            pX, Wtr + (size_t)l * TR_DIM * D_DIM, Wc + (size_t)l * CC_DIM * D_DIM);
        proj_merge_kernel<<<T_LEN / PBM, 256>>>(pAtr, pAct, pInv);
        scan_fused_kernel<<<TR_DIM, 1024, SCAN_SMEM_BYTES>>>(
            pAtr, pAct, pInv, start,
            a + (size_t)l * TR_DIM, b + (size_t)l * CC_DIM,
            state + (size_t)l * TR_DIM * CC_DIM, pScaledH);
        gemm_f16<<<ggrid, 256, SMEM_GEMM>>>(
            pScaledH, pW0h + (size_t)l * D_DIM * F_DIM, pH, T_LEN, D_DIM, F_DIM);
        ln_leaky_kernel<<<T_LEN, 128>>>(pH, b0 + (size_t)l * D_DIM,
                                        g0 + (size_t)l * D_DIM,
                                        be0 + (size_t)l * D_DIM,
                                        ISCALE0, nullptr, pHH, nullptr);
        gemm_f16<<<ggrid, 256, SMEM_GEMM>>>(
            pHH, pW1h + (size_t)l * D_DIM * D_DIM, pZ, T_LEN, D_DIM, D_DIM);
        if (l < L_NUM - 1) {
            ln_leaky_kernel<<<T_LEN, 128>>>(pZ, b1 + (size_t)l * D_DIM,
                                            g1 + (size_t)l * D_DIM,
                                            be1 + (size_t)l * D_DIM,
                                            1.0f, nullptr, nullptr, pX);
        } else {
            ln_leaky_kernel<<<T_LEN, 128>>>(pZ, b1 + (size_t)l * D_DIM,
                                            g1 + (size_t)l * D_DIM,
                                            be1 + (size_t)l * D_DIM,
                                            1.0f, out, nullptr, nullptr);
        }
    }
}